// round 1
// baseline (speedup 1.0000x reference)
#include <cuda_runtime.h>
#include <math.h>

#define NN 50000
#define NE 800000
#define F 64
#define KDIM 129      // 2*F + 1
#define KPAD 132      // padded to multiple of 4 (conflict-free: 132 % 32 == 4)
#define NB 4          // nodes per block iteration

#define ACT_NONE 0
#define ACT_RELU 1
#define ACT_SIGM 2

// ---------------- scratch (static device globals — no allocation) ----------------
__device__ int   g_cnt[NN + 1];
__device__ int   g_rowptr[NN + 1];
__device__ int   g_cursor[NN];
__device__ int   g_csr[NE];          // src indices bucketed by dst
__device__ float g_he[NN];           // segment_sum(edge_feat, dst)
__device__ float g_h0[NN * F];
__device__ float g_h1[NN * F];

// ---------------- prologue: CSR build ----------------
__global__ void zero_kernel() {
    int i = blockIdx.x * blockDim.x + threadIdx.x;
    if (i <= NN) g_cnt[i] = 0;
    if (i <  NN) g_he[i] = 0.f;
}

__global__ void hist_kernel(const float* __restrict__ ef, const int* __restrict__ dst) {
    int e = blockIdx.x * blockDim.x + threadIdx.x;
    if (e < NE) {
        int d = dst[e];
        atomicAdd(&g_cnt[d], 1);
        atomicAdd(&g_he[d], ef[e]);
    }
}

// single-block exclusive scan of g_cnt -> g_rowptr (and init g_cursor)
__global__ void scan_kernel() {
    const int T = 1024;
    int tid = threadIdx.x;
    const int chunk = (NN + T - 1) / T;   // 49
    int b0 = tid * chunk;
    int b1 = b0 + chunk; if (b1 > NN) b1 = NN;
    if (b0 > NN) b0 = NN;

    int sum = 0;
    for (int i = b0; i < b1; i++) sum += g_cnt[i];

    __shared__ int s[T];
    s[tid] = sum;
    __syncthreads();
    int val = sum;
    for (int off = 1; off < T; off <<= 1) {
        int other = (tid >= off) ? s[tid - off] : 0;
        __syncthreads();
        val += other;
        s[tid] = val;
        __syncthreads();
    }
    int run = val - sum;  // exclusive prefix
    for (int i = b0; i < b1; i++) {
        g_rowptr[i] = run;
        g_cursor[i] = run;
        run += g_cnt[i];
    }
    if (tid == T - 1) g_rowptr[NN] = run;  // total (= NE)
}

__global__ void scatter_kernel(const int* __restrict__ src, const int* __restrict__ dst) {
    int e = blockIdx.x * blockDim.x + threadIdx.x;
    if (e < NE) {
        int d = dst[e];
        int p = atomicAdd(&g_cursor[d], 1);
        g_csr[p] = src[e];
    }
}

// ---------------- fused layer: aggregate + concat + GEMM + activation ----------------
// 64 threads/block (thread t = feature channel t). NB nodes per iteration.
// W [OUTF, 129] in smem padded to KPAD; persistent blocks stride over node groups.
template <int OUTF>
__global__ void __launch_bounds__(64) layer_kernel(
    const float* __restrict__ hin,   // [NN, F]
    const float* __restrict__ W,     // [OUTF, KDIM]
    const float* __restrict__ b,     // [OUTF]
    float* __restrict__ hout,        // [NN, OUTF]
    int act)
{
    __shared__ float sW[OUTF * KPAD];
    __shared__ float sx[NB][KPAD];

    const int t = threadIdx.x;

    for (int i = t; i < OUTF * KPAD; i += 64) {
        int r = i / KPAD, c = i - r * KPAD;
        sW[i] = (c < KDIM) ? W[r * KDIM + c] : 0.f;
    }
    __syncthreads();

    const int NG = (NN + NB - 1) / NB;
    for (int g = blockIdx.x; g < NG; g += gridDim.x) {
        const int base = g * NB;

        // --- aggregation phase: build x = [h[v] | sum_{src->v} h[src] | he[v]] ---
        #pragma unroll
        for (int u = 0; u < NB; u++) {
            int v = base + u;
            if (v < NN) {
                int js = g_rowptr[v];
                int je = g_rowptr[v + 1];
                float acc = 0.f;
                int j = js;
                for (; j + 4 <= je; j += 4) {
                    int i0 = g_csr[j + 0];
                    int i1 = g_csr[j + 1];
                    int i2 = g_csr[j + 2];
                    int i3 = g_csr[j + 3];
                    float a0 = hin[i0 * F + t];
                    float a1 = hin[i1 * F + t];
                    float a2 = hin[i2 * F + t];
                    float a3 = hin[i3 * F + t];
                    acc += (a0 + a1) + (a2 + a3);
                }
                for (; j < je; j++) acc += hin[g_csr[j] * F + t];
                sx[u][t]      = hin[v * F + t];
                sx[u][F + t]  = acc;
                if (t == 0) {
                    sx[u][128] = g_he[v];
                    sx[u][129] = 0.f; sx[u][130] = 0.f; sx[u][131] = 0.f;
                }
            } else {
                sx[u][t] = 0.f;
                sx[u][F + t] = 0.f;
                if (t == 0) {
                    sx[u][128] = 0.f; sx[u][129] = 0.f; sx[u][130] = 0.f; sx[u][131] = 0.f;
                }
            }
        }
        __syncthreads();

        // --- GEMM phase: out[v][t] = b[t] + W[t,:] . x_v ---
        if (t < OUTF) {
            float o[NB];
            float bias = b[t];
            #pragma unroll
            for (int u = 0; u < NB; u++) o[u] = bias;

            const float4* wrow = reinterpret_cast<const float4*>(&sW[t * KPAD]);
            #pragma unroll
            for (int k4 = 0; k4 < KPAD / 4; k4++) {
                float4 w = wrow[k4];
                #pragma unroll
                for (int u = 0; u < NB; u++) {
                    float4 x = reinterpret_cast<const float4*>(sx[u])[k4];
                    o[u] += w.x * x.x;
                    o[u] += w.y * x.y;
                    o[u] += w.z * x.z;
                    o[u] += w.w * x.w;
                }
            }

            #pragma unroll
            for (int u = 0; u < NB; u++) {
                int v = base + u;
                if (v < NN) {
                    float r = o[u];
                    if (act == ACT_RELU)      r = fmaxf(r, 0.f);
                    else if (act == ACT_SIGM) r = 1.f / (1.f + expf(-r));
                    hout[v * OUTF + t] = r;
                }
            }
        }
        __syncthreads();
    }
}

// ---------------- launch ----------------
extern "C" void kernel_launch(void* const* d_in, const int* in_sizes, int n_in,
                              void* d_out, int out_size)
{
    const float* node_feat = (const float*)d_in[0];
    const float* edge_feat = (const float*)d_in[1];
    const int*   src       = (const int*)  d_in[2];
    const int*   dst       = (const int*)  d_in[3];
    const float* W1        = (const float*)d_in[4];
    const float* b1        = (const float*)d_in[5];
    const float* Wmid      = (const float*)d_in[6];
    const float* bmid      = (const float*)d_in[7];
    const float* W2        = (const float*)d_in[8];
    const float* b2        = (const float*)d_in[9];
    float*       out       = (float*)d_out;

    float *h0, *h1;
    cudaGetSymbolAddress((void**)&h0, g_h0);
    cudaGetSymbolAddress((void**)&h1, g_h1);

    // CSR build + he_aggr (once per replay)
    zero_kernel<<<(NN + 256) / 256, 256>>>();
    hist_kernel<<<(NE + 255) / 256, 256>>>(edge_feat, dst);
    scan_kernel<<<1, 1024>>>();
    scatter_kernel<<<(NE + 255) / 256, 256>>>(src, dst);

    // persistent grid: 6 blocks/SM (smem-limited), 148 SMs
    const int GRID64 = 148 * 6;

    // layer 1: node_feat -> h0 (relu)
    layer_kernel<F><<<GRID64, 64>>>(node_feat, W1, b1, h0, ACT_RELU);
    // mid layers 0..3 (relu), 4 (sigmoid); ping-pong h0/h1
    layer_kernel<F><<<GRID64, 64>>>(h0, Wmid + 0 * F * KDIM, bmid + 0 * F, h1, ACT_RELU);
    layer_kernel<F><<<GRID64, 64>>>(h1, Wmid + 1 * F * KDIM, bmid + 1 * F, h0, ACT_RELU);
    layer_kernel<F><<<GRID64, 64>>>(h0, Wmid + 2 * F * KDIM, bmid + 2 * F, h1, ACT_RELU);
    layer_kernel<F><<<GRID64, 64>>>(h1, Wmid + 3 * F * KDIM, bmid + 3 * F, h0, ACT_RELU);
    layer_kernel<F><<<GRID64, 64>>>(h0, Wmid + 4 * F * KDIM, bmid + 4 * F, h1, ACT_SIGM);
    // output layer: h1 -> out [NN, 2], no activation
    layer_kernel<2><<<2048, 64>>>(h1, W2, b2, out, ACT_NONE);
}

// round 3
// speedup vs baseline: 1.3487x; 1.3487x over previous
#include <cuda_runtime.h>
#include <math.h>

#define NN 50000
#define NE 800000
#define F 64
#define KDIM 129      // 2*F + 1
#define KPAD 132      // padded; stride 132 words -> conflict-free LDS.128
#define NB 16         // nodes per block iteration (4 slots x 4 sequential)
#define NG (NN / NB)  // 3125 exactly

#define ACT_NONE 0
#define ACT_RELU 1
#define ACT_SIGM 2

// ---------------- scratch (static device globals — no allocation) ----------------
__device__ int   g_cnt[NN + 1];
__device__ int   g_rowptr[NN + 1];
__device__ int   g_cursor[NN];
__device__ int   g_csr[NE];          // src indices bucketed by dst
__device__ float g_he[NN];           // segment_sum(edge_feat, dst)
__device__ float g_h0[NN * F];
__device__ float g_h1[NN * F];

// ---------------- prologue: CSR build ----------------
__global__ void zero_kernel() {
    int i = blockIdx.x * blockDim.x + threadIdx.x;
    if (i <= NN) g_cnt[i] = 0;
    if (i <  NN) g_he[i] = 0.f;
}

__global__ void hist_kernel(const float* __restrict__ ef, const int* __restrict__ dst) {
    int e = blockIdx.x * blockDim.x + threadIdx.x;
    if (e < NE) {
        int d = dst[e];
        atomicAdd(&g_cnt[d], 1);
        atomicAdd(&g_he[d], ef[e]);
    }
}

// single-block exclusive scan of g_cnt -> g_rowptr (and init g_cursor)
__global__ void scan_kernel() {
    const int T = 1024;
    int tid = threadIdx.x;
    const int chunk = (NN + T - 1) / T;
    int b0 = tid * chunk;
    int b1 = b0 + chunk; if (b1 > NN) b1 = NN;
    if (b0 > NN) b0 = NN;

    int sum = 0;
    for (int i = b0; i < b1; i++) sum += g_cnt[i];

    __shared__ int s[T];
    s[tid] = sum;
    __syncthreads();
    int val = sum;
    for (int off = 1; off < T; off <<= 1) {
        int other = (tid >= off) ? s[tid - off] : 0;
        __syncthreads();
        val += other;
        s[tid] = val;
        __syncthreads();
    }
    int run = val - sum;  // exclusive prefix
    for (int i = b0; i < b1; i++) {
        g_rowptr[i] = run;
        g_cursor[i] = run;
        run += g_cnt[i];
    }
    if (tid == T - 1) g_rowptr[NN] = run;
}

__global__ void scatter_kernel(const int* __restrict__ src, const int* __restrict__ dst) {
    int e = blockIdx.x * blockDim.x + threadIdx.x;
    if (e < NE) {
        int d = dst[e];
        int p = atomicAdd(&g_cursor[d], 1);
        g_csr[p] = src[e];
    }
}

// ---------------- fused hidden layer: aggregate + concat + GEMM(64x129) + act ----
// 256 threads: s = tid>>6 (node slot), t = tid&63 (channel).
// Each block-iter handles NB=16 nodes (slot s owns nodes base+4s .. base+4s+3).
template <int ACT>
__global__ void __launch_bounds__(256) layer64_kernel(
    const float* __restrict__ hin,   // [NN, F]
    const float* __restrict__ W,     // [F, KDIM]
    const float* __restrict__ b,     // [F]
    float* __restrict__ hout)        // [NN, F]
{
    __shared__ float sW[F * KPAD];       // 33792 B
    __shared__ float sx[NB][KPAD];       // 8448 B

    const int tid = threadIdx.x;
    const int t = tid & 63;
    const int s = tid >> 6;

    for (int i = tid; i < F * KPAD; i += 256) {
        int r = i / KPAD, c = i - r * KPAD;
        sW[i] = (c < KDIM) ? W[r * KDIM + c] : 0.f;
    }
    __syncthreads();

    const float bias = b[t];
    const float4* wrow = reinterpret_cast<const float4*>(&sW[t * KPAD]);

    for (int g = blockIdx.x; g < NG; g += gridDim.x) {
        const int base = g * NB;

        // --- aggregation: build x_v = [h[v] | sum_{src->v} h[src] | he[v]] ------
        #pragma unroll
        for (int uu = 0; uu < 4; uu++) {
            const int slot = s * 4 + uu;
            const int v = base + slot;
            const int js = g_rowptr[v];
            const int je = g_rowptr[v + 1];
            float acc = 0.f;
            int j = js;
            for (; j + 4 <= je; j += 4) {
                int i0 = g_csr[j + 0];
                int i1 = g_csr[j + 1];
                int i2 = g_csr[j + 2];
                int i3 = g_csr[j + 3];
                float a0 = hin[i0 * F + t];
                float a1 = hin[i1 * F + t];
                float a2 = hin[i2 * F + t];
                float a3 = hin[i3 * F + t];
                acc += (a0 + a1) + (a2 + a3);
            }
            for (; j < je; j++) acc += hin[g_csr[j] * F + t];
            sx[slot][t]     = hin[v * F + t];
            sx[slot][F + t] = acc;
            if (t == 0) {
                sx[slot][128] = g_he[v];
                sx[slot][129] = 0.f; sx[slot][130] = 0.f; sx[slot][131] = 0.f;
            }
        }
        __syncthreads();

        // --- GEMM: out[v][t] = b[t] + W[t,:] . x_v, 4 nodes per thread ---------
        float o0 = bias, o1 = bias, o2 = bias, o3 = bias;
        const float4* x0 = reinterpret_cast<const float4*>(sx[s * 4 + 0]);
        const float4* x1 = reinterpret_cast<const float4*>(sx[s * 4 + 1]);
        const float4* x2 = reinterpret_cast<const float4*>(sx[s * 4 + 2]);
        const float4* x3 = reinterpret_cast<const float4*>(sx[s * 4 + 3]);
        #pragma unroll
        for (int k4 = 0; k4 < KPAD / 4; k4++) {
            float4 w = wrow[k4];
            float4 a = x0[k4];
            o0 += w.x * a.x; o0 += w.y * a.y; o0 += w.z * a.z; o0 += w.w * a.w;
            float4 bb = x1[k4];
            o1 += w.x * bb.x; o1 += w.y * bb.y; o1 += w.z * bb.z; o1 += w.w * bb.w;
            float4 c = x2[k4];
            o2 += w.x * c.x; o2 += w.y * c.y; o2 += w.z * c.z; o2 += w.w * c.w;
            float4 d = x3[k4];
            o3 += w.x * d.x; o3 += w.y * d.y; o3 += w.z * d.z; o3 += w.w * d.w;
        }

        float r0 = o0, r1 = o1, r2 = o2, r3 = o3;
        if (ACT == ACT_RELU) {
            r0 = fmaxf(r0, 0.f); r1 = fmaxf(r1, 0.f);
            r2 = fmaxf(r2, 0.f); r3 = fmaxf(r3, 0.f);
        } else if (ACT == ACT_SIGM) {
            r0 = 1.f / (1.f + __expf(-r0));
            r1 = 1.f / (1.f + __expf(-r1));
            r2 = 1.f / (1.f + __expf(-r2));
            r3 = 1.f / (1.f + __expf(-r3));
        }
        hout[(base + s * 4 + 0) * F + t] = r0;
        hout[(base + s * 4 + 1) * F + t] = r1;
        hout[(base + s * 4 + 2) * F + t] = r2;
        hout[(base + s * 4 + 3) * F + t] = r3;
        __syncthreads();
    }
}

// ---------------- final layer: OUTF = 2, one warp per node --------------------
__global__ void __launch_bounds__(256) out_kernel(
    const float* __restrict__ hin,   // [NN, F]
    const float* __restrict__ W2,    // [2, KDIM]
    const float* __restrict__ b2,    // [2]
    float* __restrict__ out)         // [NN, 2]
{
    const int warp = (blockIdx.x * blockDim.x + threadIdx.x) >> 5;
    const int lane = threadIdx.x & 31;
    if (warp >= NN) return;
    const int v = warp;

    const int js = g_rowptr[v];
    const int je = g_rowptr[v + 1];
    float acc0 = 0.f, acc1 = 0.f;
    int j = js;
    for (; j + 2 <= je; j += 2) {
        int i0 = g_csr[j + 0];
        int i1 = g_csr[j + 1];
        acc0 += hin[i0 * F + lane]      + hin[i1 * F + lane];
        acc1 += hin[i0 * F + 32 + lane] + hin[i1 * F + 32 + lane];
    }
    for (; j < je; j++) {
        int i0 = g_csr[j];
        acc0 += hin[i0 * F + lane];
        acc1 += hin[i0 * F + 32 + lane];
    }
    float s0 = hin[v * F + lane];
    float s1 = hin[v * F + 32 + lane];

    float p0 = W2[lane]      * s0 + W2[32 + lane]       * s1
             + W2[64 + lane] * acc0 + W2[96 + lane]     * acc1;
    float p1 = W2[KDIM + lane]      * s0 + W2[KDIM + 32 + lane] * s1
             + W2[KDIM + 64 + lane] * acc0 + W2[KDIM + 96 + lane] * acc1;

    #pragma unroll
    for (int off = 16; off > 0; off >>= 1) {
        p0 += __shfl_xor_sync(0xffffffffu, p0, off);
        p1 += __shfl_xor_sync(0xffffffffu, p1, off);
    }
    if (lane == 0) {
        float he = g_he[v];
        out[v * 2 + 0] = p0 + W2[128]        * he + b2[0];
        out[v * 2 + 1] = p1 + W2[KDIM + 128] * he + b2[1];
    }
}

// ---------------- launch ----------------
extern "C" void kernel_launch(void* const* d_in, const int* in_sizes, int n_in,
                              void* d_out, int out_size)
{
    const float* node_feat = (const float*)d_in[0];
    const float* edge_feat = (const float*)d_in[1];
    const int*   src       = (const int*)  d_in[2];
    const int*   dst       = (const int*)  d_in[3];
    const float* W1        = (const float*)d_in[4];
    const float* b1        = (const float*)d_in[5];
    const float* Wmid      = (const float*)d_in[6];
    const float* bmid      = (const float*)d_in[7];
    const float* W2        = (const float*)d_in[8];
    const float* b2        = (const float*)d_in[9];
    float*       out       = (float*)d_out;

    float *h0, *h1;
    cudaGetSymbolAddress((void**)&h0, g_h0);
    cudaGetSymbolAddress((void**)&h1, g_h1);

    // CSR build + he_aggr
    zero_kernel<<<(NN + 256) / 256, 256>>>();
    hist_kernel<<<(NE + 255) / 256, 256>>>(edge_feat, dst);
    scan_kernel<<<1, 1024>>>();
    scatter_kernel<<<(NE + 255) / 256, 256>>>(src, dst);

    // persistent grid: 5 blocks/SM (42KB smem), 148 SMs
    const int GRID = 148 * 5;

    layer64_kernel<ACT_RELU><<<GRID, 256>>>(node_feat, W1, b1, h0);
    layer64_kernel<ACT_RELU><<<GRID, 256>>>(h0, Wmid + 0 * F * KDIM, bmid + 0 * F, h1);
    layer64_kernel<ACT_RELU><<<GRID, 256>>>(h1, Wmid + 1 * F * KDIM, bmid + 1 * F, h0);
    layer64_kernel<ACT_RELU><<<GRID, 256>>>(h0, Wmid + 2 * F * KDIM, bmid + 2 * F, h1);
    layer64_kernel<ACT_RELU><<<GRID, 256>>>(h1, Wmid + 3 * F * KDIM, bmid + 3 * F, h0);
    layer64_kernel<ACT_SIGM><<<GRID, 256>>>(h0, Wmid + 4 * F * KDIM, bmid + 4 * F, h1);
    // final layer: one warp per node
    out_kernel<<<(NN * 32 + 255) / 256, 256>>>(h1, W2, b2, out);
}

// round 4
// speedup vs baseline: 2.0780x; 1.5407x over previous
#include <cuda_runtime.h>
#include <math.h>

#define NN 50000
#define NE 800000
#define F 64
#define KDIM 129      // 2*F + 1

#define ACT_RELU 1
#define ACT_SIGM 2

// GEMM tiling
#define MT 64         // nodes per block tile
#define NT 128        // output dims (P:64 | Q:64)
#define KT 64
#define SH_STRIDE 68  // 68*4 = 272 B = 17*16 -> rows 16B-aligned, frag reads broadcast

// ---------------- scratch (static device globals — no allocation) ----------------
__device__ int   g_cnt[NN + 1];
__device__ int   g_rowptr[NN + 1];
__device__ int   g_cursor[NN];
__device__ int   g_csr[NE];             // src indices bucketed by dst
__device__ float g_he[NN];              // segment_sum(edge_feat, dst)
__device__ float g_h0[NN * F];
__device__ float g_h1[NN * F];
__device__ float g_pq[NN * NT];         // per-layer [P | Q]

// ---------------- prologue: CSR build ----------------
__global__ void zero_kernel() {
    int i = blockIdx.x * blockDim.x + threadIdx.x;
    if (i <= NN) g_cnt[i] = 0;
    if (i <  NN) g_he[i] = 0.f;
}

__global__ void hist_kernel(const float* __restrict__ ef, const int* __restrict__ dst) {
    int e = blockIdx.x * blockDim.x + threadIdx.x;
    if (e < NE) {
        int d = dst[e];
        atomicAdd(&g_cnt[d], 1);
        atomicAdd(&g_he[d], ef[e]);
    }
}

__global__ void scan_kernel() {
    const int T = 1024;
    int tid = threadIdx.x;
    const int chunk = (NN + T - 1) / T;
    int b0 = tid * chunk;
    int b1 = b0 + chunk; if (b1 > NN) b1 = NN;
    if (b0 > NN) b0 = NN;

    int sum = 0;
    for (int i = b0; i < b1; i++) sum += g_cnt[i];

    __shared__ int s[T];
    s[tid] = sum;
    __syncthreads();
    int val = sum;
    for (int off = 1; off < T; off <<= 1) {
        int other = (tid >= off) ? s[tid - off] : 0;
        __syncthreads();
        val += other;
        s[tid] = val;
        __syncthreads();
    }
    int run = val - sum;
    for (int i = b0; i < b1; i++) {
        g_rowptr[i] = run;
        g_cursor[i] = run;
        run += g_cnt[i];
    }
    if (tid == T - 1) g_rowptr[NN] = run;
}

__global__ void scatter_kernel(const int* __restrict__ src, const int* __restrict__ dst) {
    int e = blockIdx.x * blockDim.x + threadIdx.x;
    if (e < NE) {
        int d = dst[e];
        int p = atomicAdd(&g_cursor[d], 1);
        g_csr[p] = src[e];
    }
}

// ---------------- dense GEMM: PQ[u] = [A;B] . h[u]  --------------------------
// C[MT x NT] per block. 256 threads, micro-tile 8 nodes x 4 outs per thread.
// A = W[:,0:64] (self), B = W[:,64:128] (aggr). No bias (added in agg).
__global__ void __launch_bounds__(256) gemm_kernel(
    const float* __restrict__ h,    // [NN, 64]
    const float* __restrict__ W,    // [64, 129]
    float* __restrict__ PQ)         // [NN, 128]
{
    __shared__ float sh[KT][SH_STRIDE];   // h tile transposed: sh[k][node]
    __shared__ float sw[KT][NT];          // W^T: sw[k][o]

    const int tid = threadIdx.x;
    const int base = blockIdx.x * MT;

    // load W^T (o<64: A; o>=64: B)
    for (int i = tid; i < KT * NT; i += 256) {
        int k = i >> 7, o = i & 127;
        sw[k][o] = (o < F) ? W[o * KDIM + k] : W[(o - F) * KDIM + F + k];
    }
    // load h tile (transposed into sh)
    for (int i = tid; i < MT * (KT / 4); i += 256) {
        int node = i >> 4;
        int k4 = (i & 15) * 4;
        int gn = base + node;
        float4 v = (gn < NN) ? *reinterpret_cast<const float4*>(&h[gn * F + k4])
                             : make_float4(0.f, 0.f, 0.f, 0.f);
        sh[k4 + 0][node] = v.x;
        sh[k4 + 1][node] = v.y;
        sh[k4 + 2][node] = v.z;
        sh[k4 + 3][node] = v.w;
    }
    __syncthreads();

    const int tx = tid & 31;   // outs 4*tx .. 4*tx+3
    const int ty = tid >> 5;   // nodes 8*ty .. 8*ty+7

    float acc[8][4];
    #pragma unroll
    for (int i = 0; i < 8; i++)
        #pragma unroll
        for (int j = 0; j < 4; j++) acc[i][j] = 0.f;

    #pragma unroll 8
    for (int k = 0; k < KT; k++) {
        float4 a0 = *reinterpret_cast<const float4*>(&sh[k][8 * ty]);      // broadcast
        float4 a1 = *reinterpret_cast<const float4*>(&sh[k][8 * ty + 4]);  // broadcast
        float4 w  = *reinterpret_cast<const float4*>(&sw[k][4 * tx]);      // conflict-free
        float a[8] = {a0.x, a0.y, a0.z, a0.w, a1.x, a1.y, a1.z, a1.w};
        #pragma unroll
        for (int i = 0; i < 8; i++) {
            acc[i][0] += a[i] * w.x;
            acc[i][1] += a[i] * w.y;
            acc[i][2] += a[i] * w.z;
            acc[i][3] += a[i] * w.w;
        }
    }

    #pragma unroll
    for (int i = 0; i < 8; i++) {
        int gn = base + 8 * ty + i;
        if (gn < NN) {
            float4 v = make_float4(acc[i][0], acc[i][1], acc[i][2], acc[i][3]);
            *reinterpret_cast<float4*>(&PQ[gn * NT + 4 * tx]) = v;
        }
    }
}

// ---------------- aggregation: h'[v] = act(P[v] + sum Q[src] + whe*he + b) ----
// one warp per node (grid-stride), lane covers channels {2l, 2l+1}
template <int ACT>
__global__ void __launch_bounds__(256) agg_kernel(
    const float* __restrict__ PQ,    // [NN, 128]
    const float* __restrict__ W,     // [64, 129] (for whe column)
    const float* __restrict__ bias,  // [64]
    float* __restrict__ hnext)       // [NN, 64]
{
    const int gwarp  = (blockIdx.x * blockDim.x + threadIdx.x) >> 5;
    const int lane   = threadIdx.x & 31;
    const int nwarps = (gridDim.x * blockDim.x) >> 5;

    const int c0 = 2 * lane;
    const float whe0 = W[(c0 + 0) * KDIM + 128];
    const float whe1 = W[(c0 + 1) * KDIM + 128];
    const float b0 = bias[c0 + 0];
    const float b1 = bias[c0 + 1];

    for (int v = gwarp; v < NN; v += nwarps) {
        const float he = g_he[v];
        float2 p = *reinterpret_cast<const float2*>(&PQ[v * NT + c0]);
        float acc0 = p.x + b0 + whe0 * he;
        float acc1 = p.y + b1 + whe1 * he;

        const int js = g_rowptr[v];
        const int je = g_rowptr[v + 1];
        int j = js;
        for (; j + 4 <= je; j += 4) {
            int i0 = g_csr[j + 0];
            int i1 = g_csr[j + 1];
            int i2 = g_csr[j + 2];
            int i3 = g_csr[j + 3];
            float2 q0 = *reinterpret_cast<const float2*>(&PQ[i0 * NT + F + c0]);
            float2 q1 = *reinterpret_cast<const float2*>(&PQ[i1 * NT + F + c0]);
            float2 q2 = *reinterpret_cast<const float2*>(&PQ[i2 * NT + F + c0]);
            float2 q3 = *reinterpret_cast<const float2*>(&PQ[i3 * NT + F + c0]);
            acc0 += (q0.x + q1.x) + (q2.x + q3.x);
            acc1 += (q0.y + q1.y) + (q2.y + q3.y);
        }
        for (; j < je; j++) {
            int i0 = g_csr[j];
            float2 q0 = *reinterpret_cast<const float2*>(&PQ[i0 * NT + F + c0]);
            acc0 += q0.x;
            acc1 += q0.y;
        }

        if (ACT == ACT_RELU) {
            acc0 = fmaxf(acc0, 0.f);
            acc1 = fmaxf(acc1, 0.f);
        } else {
            acc0 = 1.f / (1.f + __expf(-acc0));
            acc1 = 1.f / (1.f + __expf(-acc1));
        }
        *reinterpret_cast<float2*>(&hnext[v * F + c0]) = make_float2(acc0, acc1);
    }
}

// ---------------- final layer: OUTF = 2, one warp per node --------------------
__global__ void __launch_bounds__(256) out_kernel(
    const float* __restrict__ hin,   // [NN, 64]
    const float* __restrict__ W2,    // [2, 129]
    const float* __restrict__ b2,    // [2]
    float* __restrict__ out)         // [NN, 2]
{
    const int warp = (blockIdx.x * blockDim.x + threadIdx.x) >> 5;
    const int lane = threadIdx.x & 31;
    if (warp >= NN) return;
    const int v = warp;

    const int js = g_rowptr[v];
    const int je = g_rowptr[v + 1];
    float acc0 = 0.f, acc1 = 0.f;
    int j = js;
    for (; j + 2 <= je; j += 2) {
        int i0 = g_csr[j + 0];
        int i1 = g_csr[j + 1];
        acc0 += hin[i0 * F + lane]      + hin[i1 * F + lane];
        acc1 += hin[i0 * F + 32 + lane] + hin[i1 * F + 32 + lane];
    }
    for (; j < je; j++) {
        int i0 = g_csr[j];
        acc0 += hin[i0 * F + lane];
        acc1 += hin[i0 * F + 32 + lane];
    }
    float s0 = hin[v * F + lane];
    float s1 = hin[v * F + 32 + lane];

    float p0 = W2[lane]      * s0   + W2[32 + lane] * s1
             + W2[64 + lane] * acc0 + W2[96 + lane] * acc1;
    float p1 = W2[KDIM + lane]      * s0   + W2[KDIM + 32 + lane] * s1
             + W2[KDIM + 64 + lane] * acc0 + W2[KDIM + 96 + lane] * acc1;

    #pragma unroll
    for (int off = 16; off > 0; off >>= 1) {
        p0 += __shfl_xor_sync(0xffffffffu, p0, off);
        p1 += __shfl_xor_sync(0xffffffffu, p1, off);
    }
    if (lane == 0) {
        float he = g_he[v];
        out[v * 2 + 0] = p0 + W2[128]        * he + b2[0];
        out[v * 2 + 1] = p1 + W2[KDIM + 128] * he + b2[1];
    }
}

// ---------------- launch ----------------
extern "C" void kernel_launch(void* const* d_in, const int* in_sizes, int n_in,
                              void* d_out, int out_size)
{
    const float* node_feat = (const float*)d_in[0];
    const float* edge_feat = (const float*)d_in[1];
    const int*   src       = (const int*)  d_in[2];
    const int*   dst       = (const int*)  d_in[3];
    const float* W1        = (const float*)d_in[4];
    const float* b1        = (const float*)d_in[5];
    const float* Wmid      = (const float*)d_in[6];
    const float* bmid      = (const float*)d_in[7];
    const float* W2        = (const float*)d_in[8];
    const float* b2        = (const float*)d_in[9];
    float*       out       = (float*)d_out;

    float *h0, *h1, *pq;
    cudaGetSymbolAddress((void**)&h0, g_h0);
    cudaGetSymbolAddress((void**)&h1, g_h1);
    cudaGetSymbolAddress((void**)&pq, g_pq);

    // CSR build + he_aggr
    zero_kernel<<<(NN + 256) / 256, 256>>>();
    hist_kernel<<<(NE + 255) / 256, 256>>>(edge_feat, dst);
    scan_kernel<<<1, 1024>>>();
    scatter_kernel<<<(NE + 255) / 256, 256>>>(src, dst);

    const int GEMM_GRID = (NN + MT - 1) / MT;   // 782
    const int AGG_GRID  = 148 * 16;

    // layer 1
    gemm_kernel<<<GEMM_GRID, 256>>>(node_feat, W1, pq);
    agg_kernel<ACT_RELU><<<AGG_GRID, 256>>>(pq, W1, b1, h0);
    // mid layers 0..3 (relu), 4 (sigmoid); ping-pong h0/h1
    gemm_kernel<<<GEMM_GRID, 256>>>(h0, Wmid + 0 * F * KDIM, pq);
    agg_kernel<ACT_RELU><<<AGG_GRID, 256>>>(pq, Wmid + 0 * F * KDIM, bmid + 0 * F, h1);
    gemm_kernel<<<GEMM_GRID, 256>>>(h1, Wmid + 1 * F * KDIM, pq);
    agg_kernel<ACT_RELU><<<AGG_GRID, 256>>>(pq, Wmid + 1 * F * KDIM, bmid + 1 * F, h0);
    gemm_kernel<<<GEMM_GRID, 256>>>(h0, Wmid + 2 * F * KDIM, pq);
    agg_kernel<ACT_RELU><<<AGG_GRID, 256>>>(pq, Wmid + 2 * F * KDIM, bmid + 2 * F, h1);
    gemm_kernel<<<GEMM_GRID, 256>>>(h1, Wmid + 3 * F * KDIM, pq);
    agg_kernel<ACT_RELU><<<AGG_GRID, 256>>>(pq, Wmid + 3 * F * KDIM, bmid + 3 * F, h0);
    gemm_kernel<<<GEMM_GRID, 256>>>(h0, Wmid + 4 * F * KDIM, pq);
    agg_kernel<ACT_SIGM><<<AGG_GRID, 256>>>(pq, Wmid + 4 * F * KDIM, bmid + 4 * F, h1);
    // final layer
    out_kernel<<<(NN * 32 + 255) / 256, 256>>>(h1, W2, b2, out);
}

// round 6
// speedup vs baseline: 2.2935x; 1.1037x over previous
#include <cuda_runtime.h>
#include <cuda_fp16.h>
#include <cstdint>
#include <math.h>

#define NN 50000
#define NE 800000
#define F 64
#define KDIM 129      // 2*F + 1

#define ACT_RELU 1
#define ACT_SIGM 2

// GEMM tiling
#define MT 64         // nodes per block tile
#define NT 128        // output dims (P:64 | Q:64)
#define KT 64
#define SH_STRIDE 68

// ---------------- scratch (static device globals — no allocation) ----------------
__device__ int    g_cnt[NN + 1];
__device__ int    g_rowptr[NN + 1];
__device__ int    g_rank[NE];           // rank of edge within its dst bucket
__device__ int    g_csr[NE];            // src indices bucketed by dst
__device__ float  g_he[NN];             // segment_sum(edge_feat, dst)
__device__ float  g_h0[NN * F];
__device__ float  g_h1[NN * F];
__device__ float  g_p[NN * F];          // P = A.h (self part), fp32
__device__ __half g_q[NN * F];          // Q = B.h (aggr part), fp16
__device__ float4 g_pq2[NN];            // final layer: (p2_0,p2_1,q2_0,q2_1)

// ---------------- prologue: CSR build ----------------
__global__ void zero_kernel() {
    int i = blockIdx.x * blockDim.x + threadIdx.x;
    if (i <= NN) g_cnt[i] = 0;
    if (i <  NN) g_he[i] = 0.f;
}

// counts + he scatter + per-edge rank (atomic return value)
__global__ void hist_kernel(const float* __restrict__ ef, const int* __restrict__ dst) {
    int e = blockIdx.x * blockDim.x + threadIdx.x;
    if (e < NE) {
        int d = dst[e];
        g_rank[e] = atomicAdd(&g_cnt[d], 1);
        atomicAdd(&g_he[d], ef[e]);
    }
}

__global__ void scan_kernel() {
    const int T = 1024;
    int tid = threadIdx.x;
    const int chunk = (NN + T - 1) / T;
    int b0 = tid * chunk;
    int b1 = b0 + chunk; if (b1 > NN) b1 = NN;
    if (b0 > NN) b0 = NN;

    int sum = 0;
    for (int i = b0; i < b1; i++) sum += g_cnt[i];

    __shared__ int s[T];
    s[tid] = sum;
    __syncthreads();
    int val = sum;
    for (int off = 1; off < T; off <<= 1) {
        int other = (tid >= off) ? s[tid - off] : 0;
        __syncthreads();
        val += other;
        s[tid] = val;
        __syncthreads();
    }
    int run = val - sum;
    for (int i = b0; i < b1; i++) {
        g_rowptr[i] = run;
        run += g_cnt[i];
    }
    if (tid == T - 1) g_rowptr[NN] = run;
}

// atomic-free scatter using precomputed ranks
__global__ void scatter_kernel(const int* __restrict__ src, const int* __restrict__ dst) {
    int e = blockIdx.x * blockDim.x + threadIdx.x;
    if (e < NE) {
        int d = dst[e];
        g_csr[g_rowptr[d] + g_rank[e]] = src[e];
    }
}

// ---------------- dense GEMM: [P|Q][u] = [A;B] . h[u] ------------------------
// 256 threads, micro-tile 8 nodes x 4 outs. P stored fp32, Q stored fp16.
__global__ void __launch_bounds__(256) gemm_kernel(
    const float* __restrict__ h,    // [NN, 64]
    const float* __restrict__ W)    // [64, 129]
{
    __shared__ float sh[KT][SH_STRIDE];
    __shared__ float sw[KT][NT];

    const int tid = threadIdx.x;
    const int base = blockIdx.x * MT;

    for (int i = tid; i < KT * NT; i += 256) {
        int k = i >> 7, o = i & 127;
        sw[k][o] = (o < F) ? W[o * KDIM + k] : W[(o - F) * KDIM + F + k];
    }
    for (int i = tid; i < MT * (KT / 4); i += 256) {
        int node = i >> 4;
        int k4 = (i & 15) * 4;
        int gn = base + node;
        float4 v = (gn < NN) ? *reinterpret_cast<const float4*>(&h[gn * F + k4])
                             : make_float4(0.f, 0.f, 0.f, 0.f);
        sh[k4 + 0][node] = v.x;
        sh[k4 + 1][node] = v.y;
        sh[k4 + 2][node] = v.z;
        sh[k4 + 3][node] = v.w;
    }
    __syncthreads();

    const int tx = tid & 31;   // outs 4*tx .. 4*tx+3
    const int ty = tid >> 5;   // nodes 8*ty .. 8*ty+7

    float acc[8][4];
    #pragma unroll
    for (int i = 0; i < 8; i++)
        #pragma unroll
        for (int j = 0; j < 4; j++) acc[i][j] = 0.f;

    #pragma unroll 8
    for (int k = 0; k < KT; k++) {
        float4 a0 = *reinterpret_cast<const float4*>(&sh[k][8 * ty]);
        float4 a1 = *reinterpret_cast<const float4*>(&sh[k][8 * ty + 4]);
        float4 w  = *reinterpret_cast<const float4*>(&sw[k][4 * tx]);
        float a[8] = {a0.x, a0.y, a0.z, a0.w, a1.x, a1.y, a1.z, a1.w};
        #pragma unroll
        for (int i = 0; i < 8; i++) {
            acc[i][0] += a[i] * w.x;
            acc[i][1] += a[i] * w.y;
            acc[i][2] += a[i] * w.z;
            acc[i][3] += a[i] * w.w;
        }
    }

    #pragma unroll
    for (int i = 0; i < 8; i++) {
        int gn = base + 8 * ty + i;
        if (gn < NN) {
            if (tx < 16) {
                *reinterpret_cast<float4*>(&g_p[gn * F + 4 * tx]) =
                    make_float4(acc[i][0], acc[i][1], acc[i][2], acc[i][3]);
            } else {
                __half2 a01 = __floats2half2_rn(acc[i][0], acc[i][1]);
                __half2 a23 = __floats2half2_rn(acc[i][2], acc[i][3]);
                uint2 u;
                u.x = *reinterpret_cast<unsigned int*>(&a01);
                u.y = *reinterpret_cast<unsigned int*>(&a23);
                *reinterpret_cast<uint2*>(&g_q[gn * F + 4 * (tx - 16)]) = u;
            }
        }
    }
}

// ---------------- aggregation: h'[v] = act(P[v] + sum Q[src] + whe*he + b) ----
// one warp per node, lane covers channels {2l, 2l+1}; Q gathers are fp16 (128 B/row)
template <int ACT>
__global__ void __launch_bounds__(256) agg_kernel(
    const float* __restrict__ W,     // [64, 129] (whe column)
    const float* __restrict__ bias,  // [64]
    float* __restrict__ hnext)       // [NN, 64]
{
    const int v    = (blockIdx.x * blockDim.x + threadIdx.x) >> 5;
    const int lane = threadIdx.x & 31;
    if (v >= NN) return;

    const int c0 = 2 * lane;
    const float whe0 = W[(c0 + 0) * KDIM + 128];
    const float whe1 = W[(c0 + 1) * KDIM + 128];
    const float he = g_he[v];

    float2 p = *reinterpret_cast<const float2*>(&g_p[v * F + c0]);
    float acc0 = p.x + bias[c0 + 0] + whe0 * he;
    float acc1 = p.y + bias[c0 + 1] + whe1 * he;

    const int js = g_rowptr[v];
    const int je = g_rowptr[v + 1];
    int j = js;
    for (; j + 4 <= je; j += 4) {
        int i0 = g_csr[j + 0];
        int i1 = g_csr[j + 1];
        int i2 = g_csr[j + 2];
        int i3 = g_csr[j + 3];
        float2 f0 = __half22float2(*reinterpret_cast<const __half2*>(&g_q[i0 * F + c0]));
        float2 f1 = __half22float2(*reinterpret_cast<const __half2*>(&g_q[i1 * F + c0]));
        float2 f2 = __half22float2(*reinterpret_cast<const __half2*>(&g_q[i2 * F + c0]));
        float2 f3 = __half22float2(*reinterpret_cast<const __half2*>(&g_q[i3 * F + c0]));
        acc0 += (f0.x + f1.x) + (f2.x + f3.x);
        acc1 += (f0.y + f1.y) + (f2.y + f3.y);
    }
    for (; j < je; j++) {
        float2 f = __half22float2(*reinterpret_cast<const __half2*>(&g_q[g_csr[j] * F + c0]));
        acc0 += f.x;
        acc1 += f.y;
    }

    if (ACT == ACT_RELU) {
        acc0 = fmaxf(acc0, 0.f);
        acc1 = fmaxf(acc1, 0.f);
    } else {
        acc0 = 1.f / (1.f + __expf(-acc0));
        acc1 = 1.f / (1.f + __expf(-acc1));
    }
    *reinterpret_cast<float2*>(&hnext[v * F + c0]) = make_float2(acc0, acc1);
}

// ---------------- final layer, stage 1: per-node p2/q2 (warp per node) -------
__global__ void __launch_bounds__(256) out_pre_kernel(
    const float* __restrict__ hin,   // [NN, 64]
    const float* __restrict__ W2)    // [2, 129]
{
    const int v    = (blockIdx.x * blockDim.x + threadIdx.x) >> 5;
    const int lane = threadIdx.x & 31;
    if (v >= NN) return;

    float s0 = hin[v * F + lane];
    float s1 = hin[v * F + 32 + lane];

    float p0 = W2[lane]          * s0 + W2[32 + lane]          * s1;  // self, row 0
    float p1 = W2[KDIM + lane]   * s0 + W2[KDIM + 32 + lane]   * s1;  // self, row 1
    float q0 = W2[64 + lane]     * s0 + W2[96 + lane]          * s1;  // aggr, row 0
    float q1 = W2[KDIM + 64 + lane] * s0 + W2[KDIM + 96 + lane] * s1; // aggr, row 1

    #pragma unroll
    for (int off = 16; off > 0; off >>= 1) {
        p0 += __shfl_xor_sync(0xffffffffu, p0, off);
        p1 += __shfl_xor_sync(0xffffffffu, p1, off);
        q0 += __shfl_xor_sync(0xffffffffu, q0, off);
        q1 += __shfl_xor_sync(0xffffffffu, q1, off);
    }
    if (lane == 0) g_pq2[v] = make_float4(p0, p1, q0, q1);
}

// ---------------- final layer, stage 2: edge-parallel q2 sum (warp per node) --
__global__ void __launch_bounds__(256) out_agg_kernel(
    const float* __restrict__ W2,
    const float* __restrict__ b2,
    float* __restrict__ out)         // [NN, 2]
{
    const int v    = (blockIdx.x * blockDim.x + threadIdx.x) >> 5;
    const int lane = threadIdx.x & 31;
    if (v >= NN) return;

    const int js = g_rowptr[v];
    const int je = g_rowptr[v + 1];
    float acc0 = 0.f, acc1 = 0.f;
    for (int j = js + lane; j < je; j += 32) {
        int u = g_csr[j];
        float4 pq = g_pq2[u];
        acc0 += pq.z;
        acc1 += pq.w;
    }
    #pragma unroll
    for (int off = 16; off > 0; off >>= 1) {
        acc0 += __shfl_xor_sync(0xffffffffu, acc0, off);
        acc1 += __shfl_xor_sync(0xffffffffu, acc1, off);
    }
    if (lane == 0) {
        float4 mine = g_pq2[v];
        float he = g_he[v];
        out[v * 2 + 0] = mine.x + acc0 + W2[128]        * he + b2[0];
        out[v * 2 + 1] = mine.y + acc1 + W2[KDIM + 128] * he + b2[1];
    }
}

// ---------------- launch ----------------
extern "C" void kernel_launch(void* const* d_in, const int* in_sizes, int n_in,
                              void* d_out, int out_size)
{
    const float* node_feat = (const float*)d_in[0];
    const float* edge_feat = (const float*)d_in[1];
    const int*   src       = (const int*)  d_in[2];
    const int*   dst       = (const int*)  d_in[3];
    const float* W1        = (const float*)d_in[4];
    const float* b1        = (const float*)d_in[5];
    const float* Wmid      = (const float*)d_in[6];
    const float* bmid      = (const float*)d_in[7];
    const float* W2        = (const float*)d_in[8];
    const float* b2        = (const float*)d_in[9];
    float*       out       = (float*)d_out;

    float *h0, *h1;
    cudaGetSymbolAddress((void**)&h0, g_h0);
    cudaGetSymbolAddress((void**)&h1, g_h1);

    // CSR build + he_aggr
    zero_kernel<<<(NN + 256) / 256, 256>>>();
    hist_kernel<<<(NE + 255) / 256, 256>>>(edge_feat, dst);
    scan_kernel<<<1, 1024>>>();
    scatter_kernel<<<(NE + 255) / 256, 256>>>(src, dst);

    const int GEMM_GRID = (NN + MT - 1) / MT;        // 782
    const int WPN_GRID  = (NN * 32 + 255) / 256;     // warp-per-node kernels: 6250

    gemm_kernel<<<GEMM_GRID, 256>>>(node_feat, W1);
    agg_kernel<ACT_RELU><<<WPN_GRID, 256>>>(W1, b1, h0);
    gemm_kernel<<<GEMM_GRID, 256>>>(h0, Wmid + 0 * F * KDIM);
    agg_kernel<ACT_RELU><<<WPN_GRID, 256>>>(Wmid + 0 * F * KDIM, bmid + 0 * F, h1);
    gemm_kernel<<<GEMM_GRID, 256>>>(h1, Wmid + 1 * F * KDIM);
    agg_kernel<ACT_RELU><<<WPN_GRID, 256>>>(Wmid + 1 * F * KDIM, bmid + 1 * F, h0);
    gemm_kernel<<<GEMM_GRID, 256>>>(h0, Wmid + 2 * F * KDIM);
    agg_kernel<ACT_RELU><<<WPN_GRID, 256>>>(Wmid + 2 * F * KDIM, bmid + 2 * F, h1);
    gemm_kernel<<<GEMM_GRID, 256>>>(h1, Wmid + 3 * F * KDIM);
    agg_kernel<ACT_RELU><<<WPN_GRID, 256>>>(Wmid + 3 * F * KDIM, bmid + 3 * F, h0);
    gemm_kernel<<<GEMM_GRID, 256>>>(h0, Wmid + 4 * F * KDIM);
    agg_kernel<ACT_SIGM><<<WPN_GRID, 256>>>(Wmid + 4 * F * KDIM, bmid + 4 * F, h1);

    out_pre_kernel<<<WPN_GRID, 256>>>(h1, W2);
    out_agg_kernel<<<WPN_GRID, 256>>>(W2, b2, out);
}

// round 8
// speedup vs baseline: 2.6261x; 1.1450x over previous
#include <cuda_runtime.h>
#include <cuda_fp16.h>
#include <cstdint>
#include <math.h>

#define NN 50000
#define NE 800000
#define F 64
#define KDIM 129      // 2*F + 1

#define MT 64         // nodes per GEMM block tile
#define K2 32         // 64 k's as 32 half2 pairs
#define SH_PAD 68     // half2 row stride for A tile (272 B, 16B-aligned, low conflict)

#define ACT_RELU 1
#define ACT_SIGM 2

// ---------------- scratch (static device globals — no allocation) ----------------
__device__ int    g_cnt[NN + 1];
__device__ int    g_rowptr[NN + 1];
__device__ int    g_rank[NE];
__device__ int    g_csr[NE];
__device__ float  g_he[NN];
__device__ __align__(16) __half  g_hh0[NN * F];        // fp16 hidden states (ping)
__device__ __align__(16) __half  g_hh1[NN * F];        // fp16 hidden states (pong)
__device__ __align__(16) float   g_p[NN * F];          // P = A.h (self), fp32
__device__ __align__(16) __half  g_q[NN * F];          // Q = B.h (aggr), fp16
__device__ __align__(16) __half2 g_wt[6 * K2 * 128];   // repacked fp16 weights [l][k2][n]
__device__ float4 g_pq2[NN];

// ---------------- prologue: CSR build ----------------
__global__ void hist_kernel(const float* __restrict__ ef, const int* __restrict__ dst) {
    int e = blockIdx.x * blockDim.x + threadIdx.x;
    if (e < NE) {
        int d = dst[e];
        g_rank[e] = atomicAdd(&g_cnt[d], 1);
        atomicAdd(&g_he[d], ef[e]);
    }
}

__global__ void scan_kernel() {
    const int T = 1024;
    int tid = threadIdx.x;
    const int chunk = (NN + T - 1) / T;
    int b0 = tid * chunk;
    int b1 = b0 + chunk; if (b1 > NN) b1 = NN;
    if (b0 > NN) b0 = NN;

    int sum = 0;
    for (int i = b0; i < b1; i++) sum += g_cnt[i];

    __shared__ int s[T];
    s[tid] = sum;
    __syncthreads();
    int val = sum;
    for (int off = 1; off < T; off <<= 1) {
        int other = (tid >= off) ? s[tid - off] : 0;
        __syncthreads();
        val += other;
        s[tid] = val;
        __syncthreads();
    }
    int run = val - sum;
    for (int i = b0; i < b1; i++) {
        g_rowptr[i] = run;
        run += g_cnt[i];
    }
    if (tid == T - 1) g_rowptr[NN] = run;
}

__global__ void scatter_kernel(const int* __restrict__ src, const int* __restrict__ dst) {
    int e = blockIdx.x * blockDim.x + threadIdx.x;
    if (e < NE) {
        int d = dst[e];
        g_csr[g_rowptr[d] + g_rank[e]] = src[e];
    }
}

// ---------------- converts ----------------
__global__ void convert_h_kernel(const float* __restrict__ in) {
    int i = blockIdx.x * blockDim.x + threadIdx.x;
    if (i < NN * F / 2) {
        float2 v = reinterpret_cast<const float2*>(in)[i];
        reinterpret_cast<__half2*>(g_hh0)[i] = __floats2half2_rn(v.x, v.y);
    }
}

// repack weights transposed: g_wt[l][k2][n] = half2(Weff[n][2k2], Weff[n][2k2+1])
// Weff[n][k] = n<64 ? Wl[n][k] : Wl[n-64][64+k]
__global__ void convert_w_kernel(const float* __restrict__ W1, const float* __restrict__ Wmid) {
    int idx = blockIdx.x * blockDim.x + threadIdx.x;
    if (idx < 6 * K2 * 128) {
        int l = idx >> 12;
        int rem = idx & 4095;
        int k2 = rem >> 7;
        int n = rem & 127;
        const float* Wl = (l == 0) ? W1 : (Wmid + (l - 1) * F * KDIM);
        int k = 2 * k2;
        float v0, v1;
        if (n < F) { v0 = Wl[n * KDIM + k];            v1 = Wl[n * KDIM + k + 1]; }
        else       { v0 = Wl[(n - F) * KDIM + F + k];  v1 = Wl[(n - F) * KDIM + F + k + 1]; }
        g_wt[idx] = __floats2half2_rn(v0, v1);
    }
}

// ---------------- half2 GEMM: [P|Q][u] = Weff . h[u] -------------------------
// 256 threads; tx = tid&31 (outs 4tx..4tx+3), ty = tid>>5 (nodes 8ty..8ty+7).
// fp16 products/accumulation in 32-k chunks, flushed to fp32 (2 chunks).
__global__ void __launch_bounds__(256) gemm_h2_kernel(
    const __half* __restrict__ hh,     // [NN, 64] fp16
    const __half2* __restrict__ wt)    // [K2, 128] repacked
{
    __shared__ __half2 sh2[K2][SH_PAD];   // A: [k2][node]
    __shared__ __half2 sw2[K2][128];      // W: [k2][out]

    const int tid = threadIdx.x;
    const int base = blockIdx.x * MT;

    for (int i = tid; i < K2 * 128; i += 256)
        reinterpret_cast<__half2*>(sw2)[ (i >> 7) * 128 + (i & 127) ] = wt[i];

    for (int i = tid; i < MT * K2; i += 256) {
        int node = i >> 5, k2 = i & 31;
        int gn = base + node;
        __half2 v = __float2half2_rn(0.f);
        if (gn < NN) v = *reinterpret_cast<const __half2*>(&hh[gn * F + 2 * k2]);
        sh2[k2][node] = v;
    }
    __syncthreads();

    const int tx = tid & 31;
    const int ty = tid >> 5;

    float accf[8][4];
    #pragma unroll
    for (int i = 0; i < 8; i++)
        #pragma unroll
        for (int j = 0; j < 4; j++) accf[i][j] = 0.f;

    #pragma unroll
    for (int chunk = 0; chunk < 2; chunk++) {
        __half2 acc2[8][4];
        #pragma unroll
        for (int i = 0; i < 8; i++)
            #pragma unroll
            for (int j = 0; j < 4; j++) acc2[i][j] = __float2half2_rn(0.f);

        #pragma unroll
        for (int kk = 0; kk < 16; kk++) {
            const int k2 = chunk * 16 + kk;
            __half2 a[8];
            *reinterpret_cast<uint4*>(a)     = *reinterpret_cast<const uint4*>(&sh2[k2][8 * ty]);
            *reinterpret_cast<uint4*>(a + 4) = *reinterpret_cast<const uint4*>(&sh2[k2][8 * ty + 4]);
            __half2 w[4];
            *reinterpret_cast<uint4*>(w) = *reinterpret_cast<const uint4*>(&sw2[k2][4 * tx]);
            #pragma unroll
            for (int i = 0; i < 8; i++) {
                acc2[i][0] = __hfma2(a[i], w[0], acc2[i][0]);
                acc2[i][1] = __hfma2(a[i], w[1], acc2[i][1]);
                acc2[i][2] = __hfma2(a[i], w[2], acc2[i][2]);
                acc2[i][3] = __hfma2(a[i], w[3], acc2[i][3]);
            }
        }
        #pragma unroll
        for (int i = 0; i < 8; i++)
            #pragma unroll
            for (int j = 0; j < 4; j++) {
                float2 f = __half22float2(acc2[i][j]);
                accf[i][j] += f.x + f.y;
            }
    }

    // epilogue: outs 4tx..4tx+3; cols<64 -> P fp32, cols>=64 -> Q fp16
    #pragma unroll
    for (int i = 0; i < 8; i++) {
        int gn = base + 8 * ty + i;
        if (gn < NN) {
            if (tx < 16) {
                *reinterpret_cast<float4*>(&g_p[gn * F + 4 * tx]) =
                    make_float4(accf[i][0], accf[i][1], accf[i][2], accf[i][3]);
            } else {
                __half2 h0 = __floats2half2_rn(accf[i][0], accf[i][1]);
                __half2 h1 = __floats2half2_rn(accf[i][2], accf[i][3]);
                uint2 u;
                u.x = *reinterpret_cast<unsigned*>(&h0);
                u.y = *reinterpret_cast<unsigned*>(&h1);
                *reinterpret_cast<uint2*>(&g_q[gn * F + 4 * (tx - 16)]) = u;
            }
        }
    }
}

// ---------------- aggregation (relu layers): h'[v] = relu(P + sumQ + whe*he + b)
__global__ void __launch_bounds__(256) agg_relu_kernel(
    const float* __restrict__ W,
    const float* __restrict__ bias,
    __half* __restrict__ hnext)
{
    const int v    = (blockIdx.x * blockDim.x + threadIdx.x) >> 5;
    const int lane = threadIdx.x & 31;
    if (v >= NN) return;

    const int c0 = 2 * lane;
    const float whe0 = W[(c0 + 0) * KDIM + 128];
    const float whe1 = W[(c0 + 1) * KDIM + 128];
    const float he = g_he[v];

    float2 p = *reinterpret_cast<const float2*>(&g_p[v * F + c0]);
    float acc0 = p.x + bias[c0 + 0] + whe0 * he;
    float acc1 = p.y + bias[c0 + 1] + whe1 * he;

    const int js = g_rowptr[v];
    const int je = g_rowptr[v + 1];
    int j = js;
    for (; j + 8 <= je; j += 8) {
        int idx[8];
        #pragma unroll
        for (int u = 0; u < 8; u++) idx[u] = g_csr[j + u];
        float2 f[8];
        #pragma unroll
        for (int u = 0; u < 8; u++)
            f[u] = __half22float2(*reinterpret_cast<const __half2*>(&g_q[idx[u] * F + c0]));
        #pragma unroll
        for (int u = 0; u < 8; u++) { acc0 += f[u].x; acc1 += f[u].y; }
    }
    for (; j < je; j++) {
        float2 f = __half22float2(*reinterpret_cast<const __half2*>(&g_q[g_csr[j] * F + c0]));
        acc0 += f.x;
        acc1 += f.y;
    }

    acc0 = fmaxf(acc0, 0.f);
    acc1 = fmaxf(acc1, 0.f);
    *reinterpret_cast<__half2*>(&hnext[v * F + c0]) = __floats2half2_rn(acc0, acc1);
}

// ---------------- final hidden layer agg (sigmoid) fused with out_pre ---------
// computes h7[v] in-warp, immediately forms p2/q2 partials and reduces.
__global__ void __launch_bounds__(256) agg_sigm_out_kernel(
    const float* __restrict__ W,     // Wmid[4]
    const float* __restrict__ bias,  // bmid[4]
    const float* __restrict__ W2)    // [2, 129]
{
    const int v    = (blockIdx.x * blockDim.x + threadIdx.x) >> 5;
    const int lane = threadIdx.x & 31;
    if (v >= NN) return;

    const int c0 = 2 * lane;
    const float whe0 = W[(c0 + 0) * KDIM + 128];
    const float whe1 = W[(c0 + 1) * KDIM + 128];
    const float he = g_he[v];

    float2 p = *reinterpret_cast<const float2*>(&g_p[v * F + c0]);
    float acc0 = p.x + bias[c0 + 0] + whe0 * he;
    float acc1 = p.y + bias[c0 + 1] + whe1 * he;

    const int js = g_rowptr[v];
    const int je = g_rowptr[v + 1];
    int j = js;
    for (; j + 8 <= je; j += 8) {
        int idx[8];
        #pragma unroll
        for (int u = 0; u < 8; u++) idx[u] = g_csr[j + u];
        float2 f[8];
        #pragma unroll
        for (int u = 0; u < 8; u++)
            f[u] = __half22float2(*reinterpret_cast<const __half2*>(&g_q[idx[u] * F + c0]));
        #pragma unroll
        for (int u = 0; u < 8; u++) { acc0 += f[u].x; acc1 += f[u].y; }
    }
    for (; j < je; j++) {
        float2 f = __half22float2(*reinterpret_cast<const __half2*>(&g_q[g_csr[j] * F + c0]));
        acc0 += f.x;
        acc1 += f.y;
    }

    const float h0 = 1.f / (1.f + __expf(-acc0));
    const float h1 = 1.f / (1.f + __expf(-acc1));

    // out_pre fused: p2 = W2[:,0:64].h ; q2 = W2[:,64:128].h
    float p0 = W2[c0] * h0 + W2[c0 + 1] * h1;
    float p1 = W2[KDIM + c0] * h0 + W2[KDIM + c0 + 1] * h1;
    float q0 = W2[64 + c0] * h0 + W2[64 + c0 + 1] * h1;
    float q1 = W2[KDIM + 64 + c0] * h0 + W2[KDIM + 64 + c0 + 1] * h1;

    #pragma unroll
    for (int off = 16; off > 0; off >>= 1) {
        p0 += __shfl_xor_sync(0xffffffffu, p0, off);
        p1 += __shfl_xor_sync(0xffffffffu, p1, off);
        q0 += __shfl_xor_sync(0xffffffffu, q0, off);
        q1 += __shfl_xor_sync(0xffffffffu, q1, off);
    }
    if (lane == 0) g_pq2[v] = make_float4(p0, p1, q0, q1);
}

// ---------------- final layer: edge-parallel q2 sum --------------------------
__global__ void __launch_bounds__(256) out_agg_kernel(
    const float* __restrict__ W2,
    const float* __restrict__ b2,
    float* __restrict__ out)
{
    const int v    = (blockIdx.x * blockDim.x + threadIdx.x) >> 5;
    const int lane = threadIdx.x & 31;
    if (v >= NN) return;

    const int js = g_rowptr[v];
    const int je = g_rowptr[v + 1];
    float acc0 = 0.f, acc1 = 0.f;
    for (int j = js + lane; j < je; j += 32) {
        float4 pq = g_pq2[g_csr[j]];
        acc0 += pq.z;
        acc1 += pq.w;
    }
    #pragma unroll
    for (int off = 16; off > 0; off >>= 1) {
        acc0 += __shfl_xor_sync(0xffffffffu, acc0, off);
        acc1 += __shfl_xor_sync(0xffffffffu, acc1, off);
    }
    if (lane == 0) {
        float4 mine = g_pq2[v];
        float he = g_he[v];
        out[v * 2 + 0] = mine.x + acc0 + W2[128]        * he + b2[0];
        out[v * 2 + 1] = mine.y + acc1 + W2[KDIM + 128] * he + b2[1];
    }
}

// ---------------- launch ----------------
extern "C" void kernel_launch(void* const* d_in, const int* in_sizes, int n_in,
                              void* d_out, int out_size)
{
    const float* node_feat = (const float*)d_in[0];
    const float* edge_feat = (const float*)d_in[1];
    const int*   src       = (const int*)  d_in[2];
    const int*   dst       = (const int*)  d_in[3];
    const float* W1        = (const float*)d_in[4];
    const float* b1        = (const float*)d_in[5];
    const float* Wmid      = (const float*)d_in[6];
    const float* bmid      = (const float*)d_in[7];
    const float* W2        = (const float*)d_in[8];
    const float* b2        = (const float*)d_in[9];
    float*       out       = (float*)d_out;

    __half *hh0, *hh1;
    __half2* wt;
    void *cnt_ptr, *he_ptr;
    cudaGetSymbolAddress((void**)&hh0, g_hh0);
    cudaGetSymbolAddress((void**)&hh1, g_hh1);
    cudaGetSymbolAddress((void**)&wt,  g_wt);
    cudaGetSymbolAddress(&cnt_ptr, g_cnt);
    cudaGetSymbolAddress(&he_ptr,  g_he);

    // CSR build + he_aggr + converts
    cudaMemsetAsync(cnt_ptr, 0, (NN + 1) * sizeof(int));
    cudaMemsetAsync(he_ptr,  0, NN * sizeof(float));
    hist_kernel<<<(NE + 255) / 256, 256>>>(edge_feat, dst);
    convert_w_kernel<<<(6 * K2 * 128 + 255) / 256, 256>>>(W1, Wmid);
    convert_h_kernel<<<(NN * F / 2 + 255) / 256, 256>>>(node_feat);
    scan_kernel<<<1, 1024>>>();
    scatter_kernel<<<(NE + 255) / 256, 256>>>(src, dst);

    const int GEMM_GRID = (NN + MT - 1) / MT;        // 782
    const int WPN_GRID  = (NN * 32 + 255) / 256;     // warp-per-node: 6250

    gemm_h2_kernel<<<GEMM_GRID, 256>>>(hh0, wt + 0 * K2 * 128);
    agg_relu_kernel<<<WPN_GRID, 256>>>(W1, b1, hh1);
    gemm_h2_kernel<<<GEMM_GRID, 256>>>(hh1, wt + 1 * K2 * 128);
    agg_relu_kernel<<<WPN_GRID, 256>>>(Wmid + 0 * F * KDIM, bmid + 0 * F, hh0);
    gemm_h2_kernel<<<GEMM_GRID, 256>>>(hh0, wt + 2 * K2 * 128);
    agg_relu_kernel<<<WPN_GRID, 256>>>(Wmid + 1 * F * KDIM, bmid + 1 * F, hh1);
    gemm_h2_kernel<<<GEMM_GRID, 256>>>(hh1, wt + 3 * K2 * 128);
    agg_relu_kernel<<<WPN_GRID, 256>>>(Wmid + 2 * F * KDIM, bmid + 2 * F, hh0);
    gemm_h2_kernel<<<GEMM_GRID, 256>>>(hh0, wt + 4 * K2 * 128);
    agg_relu_kernel<<<WPN_GRID, 256>>>(Wmid + 3 * F * KDIM, bmid + 3 * F, hh1);
    gemm_h2_kernel<<<GEMM_GRID, 256>>>(hh1, wt + 5 * K2 * 128);
    agg_sigm_out_kernel<<<WPN_GRID, 256>>>(Wmid + 4 * F * KDIM, bmid + 4 * F, W2);

    out_agg_kernel<<<WPN_GRID, 256>>>(W2, b2, out);
}

// round 9
// speedup vs baseline: 2.9037x; 1.1057x over previous
#include <cuda_runtime.h>
#include <cuda_fp16.h>
#include <cstdint>
#include <math.h>

#define NN 50000
#define NE 800000
#define F 64
#define KDIM 129      // 2*F + 1

#define MT 64         // nodes per GEMM block tile
#define K2 32         // 64 k's as 32 half2 pairs
#define SH_PAD 68

#define SCAN_CHUNK 256
#define SCAN_NBLK ((NN + SCAN_CHUNK - 1) / SCAN_CHUNK)   // 196

// ---------------- scratch (static device globals — no allocation) ----------------
__device__ int    g_cnt[NN + 1];
__device__ int    g_rowptr[NN + 1];
__device__ int    g_rank[NE];
__device__ int    g_csr[NE];
__device__ int    g_bsum[SCAN_NBLK];
__device__ int    g_boff[SCAN_NBLK];
__device__ float  g_he[NN];
__device__ __align__(16) __half  g_hh0[NN * F];
__device__ __align__(16) __half  g_hh1[NN * F];
__device__ __align__(16) float   g_p[NN * F];
__device__ __align__(16) __half  g_q[NN * F];
__device__ __align__(16) __half2 g_wt[6 * K2 * 128];
__device__ float4 g_pq2[NN];

// ---------------- prologue: CSR build ----------------
__global__ void hist_kernel(const float* __restrict__ ef, const int* __restrict__ dst) {
    int e = blockIdx.x * blockDim.x + threadIdx.x;
    if (e < NE) {
        int d = dst[e];
        g_rank[e] = atomicAdd(&g_cnt[d], 1);
        atomicAdd(&g_he[d], ef[e]);
    }
}

// block-wide inclusive scan of v (256 threads); returns inclusive prefix
__device__ __forceinline__ int block_incl_scan(int v, int* smem) {
    const int t = threadIdx.x, lane = t & 31, w = t >> 5;
    int incl = v;
    #pragma unroll
    for (int off = 1; off < 32; off <<= 1) {
        int n = __shfl_up_sync(0xffffffffu, incl, off);
        if (lane >= off) incl += n;
    }
    if (lane == 31) smem[w] = incl;
    __syncthreads();
    if (w == 0) {
        int s = (lane < 8) ? smem[lane] : 0;
        #pragma unroll
        for (int off = 1; off < 8; off <<= 1) {
            int n = __shfl_up_sync(0xffffffffu, s, off);
            if (lane >= off) s += n;
        }
        if (lane < 8) smem[lane] = s;
    }
    __syncthreads();
    if (w > 0) incl += smem[w - 1];
    return incl;
}

// pass 1: per-block sums of g_cnt
__global__ void __launch_bounds__(256) scan1_kernel() {
    __shared__ int smem[8];
    int i = blockIdx.x * SCAN_CHUNK + threadIdx.x;
    int v = (i < NN) ? g_cnt[i] : 0;
    int incl = block_incl_scan(v, smem);
    if (threadIdx.x == 255) g_bsum[blockIdx.x] = incl;
}

// pass 2: single-block exclusive scan of block sums
__global__ void __launch_bounds__(256) scan2_kernel() {
    __shared__ int smem[8];
    int t = threadIdx.x;
    int v = (t < SCAN_NBLK) ? g_bsum[t] : 0;
    int incl = block_incl_scan(v, smem);
    if (t < SCAN_NBLK) g_boff[t] = incl - v;
    if (t == SCAN_NBLK - 1) g_rowptr[NN] = incl;
}

// pass 3: per-element exclusive prefix + block offset
__global__ void __launch_bounds__(256) scan3_kernel() {
    __shared__ int smem[8];
    int i = blockIdx.x * SCAN_CHUNK + threadIdx.x;
    int v = (i < NN) ? g_cnt[i] : 0;
    int incl = block_incl_scan(v, smem);
    if (i < NN) g_rowptr[i] = g_boff[blockIdx.x] + incl - v;
}

__global__ void scatter_kernel(const int* __restrict__ src, const int* __restrict__ dst) {
    int e = blockIdx.x * blockDim.x + threadIdx.x;
    if (e < NE) {
        int d = dst[e];
        g_csr[g_rowptr[d] + g_rank[e]] = src[e];
    }
}

// ---------------- weight repack ----------------
__global__ void convert_w_kernel(const float* __restrict__ W1, const float* __restrict__ Wmid) {
    int idx = blockIdx.x * blockDim.x + threadIdx.x;
    if (idx < 6 * K2 * 128) {
        int l = idx >> 12;
        int rem = idx & 4095;
        int k2 = rem >> 7;
        int n = rem & 127;
        const float* Wl = (l == 0) ? W1 : (Wmid + (l - 1) * F * KDIM);
        int k = 2 * k2;
        float v0, v1;
        if (n < F) { v0 = Wl[n * KDIM + k];            v1 = Wl[n * KDIM + k + 1]; }
        else       { v0 = Wl[(n - F) * KDIM + F + k];  v1 = Wl[(n - F) * KDIM + F + k + 1]; }
        g_wt[idx] = __floats2half2_rn(v0, v1);
    }
}

// ---------------- half2 GEMM: [P|Q][u] = Weff . h[u] -------------------------
// FP32IN: read fp32 input (first layer) instead of fp16 hidden state.
template <bool FP32IN>
__global__ void __launch_bounds__(256) gemm_h2_kernel(
    const void* __restrict__ hin,
    const __half2* __restrict__ wt)
{
    __shared__ __half2 sh2[K2][SH_PAD];
    __shared__ __half2 sw2[K2][128];

    const int tid = threadIdx.x;
    const int base = blockIdx.x * MT;

    for (int i = tid; i < K2 * 128; i += 256)
        reinterpret_cast<__half2*>(sw2)[(i >> 7) * 128 + (i & 127)] = wt[i];

    for (int i = tid; i < MT * K2; i += 256) {
        int node = i >> 5, k2 = i & 31;
        int gn = base + node;
        __half2 v = __float2half2_rn(0.f);
        if (gn < NN) {
            if (FP32IN) {
                float2 f = *reinterpret_cast<const float2*>(
                    reinterpret_cast<const float*>(hin) + gn * F + 2 * k2);
                v = __floats2half2_rn(f.x, f.y);
            } else {
                v = *reinterpret_cast<const __half2*>(
                    reinterpret_cast<const __half*>(hin) + gn * F + 2 * k2);
            }
        }
        sh2[k2][node] = v;
    }
    __syncthreads();

    const int tx = tid & 31;
    const int ty = tid >> 5;

    float accf[8][4];
    #pragma unroll
    for (int i = 0; i < 8; i++)
        #pragma unroll
        for (int j = 0; j < 4; j++) accf[i][j] = 0.f;

    #pragma unroll
    for (int chunk = 0; chunk < 2; chunk++) {
        __half2 acc2[8][4];
        #pragma unroll
        for (int i = 0; i < 8; i++)
            #pragma unroll
            for (int j = 0; j < 4; j++) acc2[i][j] = __float2half2_rn(0.f);

        #pragma unroll
        for (int kk = 0; kk < 16; kk++) {
            const int k2 = chunk * 16 + kk;
            __half2 a[8];
            *reinterpret_cast<uint4*>(a)     = *reinterpret_cast<const uint4*>(&sh2[k2][8 * ty]);
            *reinterpret_cast<uint4*>(a + 4) = *reinterpret_cast<const uint4*>(&sh2[k2][8 * ty + 4]);
            __half2 w[4];
            *reinterpret_cast<uint4*>(w) = *reinterpret_cast<const uint4*>(&sw2[k2][4 * tx]);
            #pragma unroll
            for (int i = 0; i < 8; i++) {
                acc2[i][0] = __hfma2(a[i], w[0], acc2[i][0]);
                acc2[i][1] = __hfma2(a[i], w[1], acc2[i][1]);
                acc2[i][2] = __hfma2(a[i], w[2], acc2[i][2]);
                acc2[i][3] = __hfma2(a[i], w[3], acc2[i][3]);
            }
        }
        #pragma unroll
        for (int i = 0; i < 8; i++)
            #pragma unroll
            for (int j = 0; j < 4; j++) {
                float2 f = __half22float2(acc2[i][j]);
                accf[i][j] += f.x + f.y;
            }
    }

    #pragma unroll
    for (int i = 0; i < 8; i++) {
        int gn = base + 8 * ty + i;
        if (gn < NN) {
            if (tx < 16) {
                *reinterpret_cast<float4*>(&g_p[gn * F + 4 * tx]) =
                    make_float4(accf[i][0], accf[i][1], accf[i][2], accf[i][3]);
            } else {
                __half2 h0 = __floats2half2_rn(accf[i][0], accf[i][1]);
                __half2 h1 = __floats2half2_rn(accf[i][2], accf[i][3]);
                uint2 u;
                u.x = *reinterpret_cast<unsigned*>(&h0);
                u.y = *reinterpret_cast<unsigned*>(&h1);
                *reinterpret_cast<uint2*>(&g_q[gn * F + 4 * (tx - 16)]) = u;
            }
        }
    }
}

// ---------------- aggregation (relu): h'[v] = relu(P + sumQ + whe*he + b) ----
__global__ void __launch_bounds__(256) agg_relu_kernel(
    const float* __restrict__ W,
    const float* __restrict__ bias,
    __half* __restrict__ hnext)
{
    const int v    = (blockIdx.x * blockDim.x + threadIdx.x) >> 5;
    const int lane = threadIdx.x & 31;
    if (v >= NN) return;

    const int c0 = 2 * lane;
    const float whe0 = W[(c0 + 0) * KDIM + 128];
    const float whe1 = W[(c0 + 1) * KDIM + 128];
    const float he = g_he[v];

    float2 p = *reinterpret_cast<const float2*>(&g_p[v * F + c0]);
    float acc0 = p.x + bias[c0 + 0] + whe0 * he;
    float acc1 = p.y + bias[c0 + 1] + whe1 * he;

    const int js = g_rowptr[v];
    const int je = g_rowptr[v + 1];
    int j = js;
    for (; j + 8 <= je; j += 8) {
        int idx[8];
        #pragma unroll
        for (int u = 0; u < 8; u++) idx[u] = g_csr[j + u];
        float2 f[8];
        #pragma unroll
        for (int u = 0; u < 8; u++)
            f[u] = __half22float2(*reinterpret_cast<const __half2*>(&g_q[idx[u] * F + c0]));
        #pragma unroll
        for (int u = 0; u < 8; u++) { acc0 += f[u].x; acc1 += f[u].y; }
    }
    for (; j < je; j++) {
        float2 f = __half22float2(*reinterpret_cast<const __half2*>(&g_q[g_csr[j] * F + c0]));
        acc0 += f.x;
        acc1 += f.y;
    }

    acc0 = fmaxf(acc0, 0.f);
    acc1 = fmaxf(acc1, 0.f);
    *reinterpret_cast<__half2*>(&hnext[v * F + c0]) = __floats2half2_rn(acc0, acc1);
}

// ---------------- final hidden agg (sigmoid) fused with out_pre ---------------
__global__ void __launch_bounds__(256) agg_sigm_out_kernel(
    const float* __restrict__ W,
    const float* __restrict__ bias,
    const float* __restrict__ W2)
{
    const int v    = (blockIdx.x * blockDim.x + threadIdx.x) >> 5;
    const int lane = threadIdx.x & 31;
    if (v >= NN) return;

    const int c0 = 2 * lane;
    const float whe0 = W[(c0 + 0) * KDIM + 128];
    const float whe1 = W[(c0 + 1) * KDIM + 128];
    const float he = g_he[v];

    float2 p = *reinterpret_cast<const float2*>(&g_p[v * F + c0]);
    float acc0 = p.x + bias[c0 + 0] + whe0 * he;
    float acc1 = p.y + bias[c0 + 1] + whe1 * he;

    const int js = g_rowptr[v];
    const int je = g_rowptr[v + 1];
    int j = js;
    for (; j + 8 <= je; j += 8) {
        int idx[8];
        #pragma unroll
        for (int u = 0; u < 8; u++) idx[u] = g_csr[j + u];
        float2 f[8];
        #pragma unroll
        for (int u = 0; u < 8; u++)
            f[u] = __half22float2(*reinterpret_cast<const __half2*>(&g_q[idx[u] * F + c0]));
        #pragma unroll
        for (int u = 0; u < 8; u++) { acc0 += f[u].x; acc1 += f[u].y; }
    }
    for (; j < je; j++) {
        float2 f = __half22float2(*reinterpret_cast<const __half2*>(&g_q[g_csr[j] * F + c0]));
        acc0 += f.x;
        acc1 += f.y;
    }

    const float h0 = 1.f / (1.f + __expf(-acc0));
    const float h1 = 1.f / (1.f + __expf(-acc1));

    float p0 = W2[c0] * h0 + W2[c0 + 1] * h1;
    float p1 = W2[KDIM + c0] * h0 + W2[KDIM + c0 + 1] * h1;
    float q0 = W2[64 + c0] * h0 + W2[64 + c0 + 1] * h1;
    float q1 = W2[KDIM + 64 + c0] * h0 + W2[KDIM + 64 + c0 + 1] * h1;

    #pragma unroll
    for (int off = 16; off > 0; off >>= 1) {
        p0 += __shfl_xor_sync(0xffffffffu, p0, off);
        p1 += __shfl_xor_sync(0xffffffffu, p1, off);
        q0 += __shfl_xor_sync(0xffffffffu, q0, off);
        q1 += __shfl_xor_sync(0xffffffffu, q1, off);
    }
    if (lane == 0) g_pq2[v] = make_float4(p0, p1, q0, q1);
}

// ---------------- final layer: edge-parallel q2 sum --------------------------
__global__ void __launch_bounds__(256) out_agg_kernel(
    const float* __restrict__ W2,
    const float* __restrict__ b2,
    float* __restrict__ out)
{
    const int v    = (blockIdx.x * blockDim.x + threadIdx.x) >> 5;
    const int lane = threadIdx.x & 31;
    if (v >= NN) return;

    const int js = g_rowptr[v];
    const int je = g_rowptr[v + 1];
    float acc0 = 0.f, acc1 = 0.f;
    for (int j = js + lane; j < je; j += 32) {
        float4 pq = g_pq2[g_csr[j]];
        acc0 += pq.z;
        acc1 += pq.w;
    }
    #pragma unroll
    for (int off = 16; off > 0; off >>= 1) {
        acc0 += __shfl_xor_sync(0xffffffffu, acc0, off);
        acc1 += __shfl_xor_sync(0xffffffffu, acc1, off);
    }
    if (lane == 0) {
        float4 mine = g_pq2[v];
        float he = g_he[v];
        out[v * 2 + 0] = mine.x + acc0 + W2[128]        * he + b2[0];
        out[v * 2 + 1] = mine.y + acc1 + W2[KDIM + 128] * he + b2[1];
    }
}

// ---------------- launch ----------------
extern "C" void kernel_launch(void* const* d_in, const int* in_sizes, int n_in,
                              void* d_out, int out_size)
{
    const float* node_feat = (const float*)d_in[0];
    const float* edge_feat = (const float*)d_in[1];
    const int*   src       = (const int*)  d_in[2];
    const int*   dst       = (const int*)  d_in[3];
    const float* W1        = (const float*)d_in[4];
    const float* b1        = (const float*)d_in[5];
    const float* Wmid      = (const float*)d_in[6];
    const float* bmid      = (const float*)d_in[7];
    const float* W2        = (const float*)d_in[8];
    const float* b2        = (const float*)d_in[9];
    float*       out       = (float*)d_out;

    __half *hh0, *hh1;
    __half2* wt;
    void *cnt_ptr, *he_ptr;
    cudaGetSymbolAddress((void**)&hh0, g_hh0);
    cudaGetSymbolAddress((void**)&hh1, g_hh1);
    cudaGetSymbolAddress((void**)&wt,  g_wt);
    cudaGetSymbolAddress(&cnt_ptr, g_cnt);
    cudaGetSymbolAddress(&he_ptr,  g_he);

    cudaMemsetAsync(cnt_ptr, 0, (NN + 1) * sizeof(int));
    cudaMemsetAsync(he_ptr,  0, NN * sizeof(float));
    hist_kernel<<<(NE + 255) / 256, 256>>>(edge_feat, dst);
    convert_w_kernel<<<(6 * K2 * 128 + 255) / 256, 256>>>(W1, Wmid);
    scan1_kernel<<<SCAN_NBLK, 256>>>();
    scan2_kernel<<<1, 256>>>();
    scan3_kernel<<<SCAN_NBLK, 256>>>();
    scatter_kernel<<<(NE + 255) / 256, 256>>>(src, dst);

    const int GEMM_GRID = (NN + MT - 1) / MT;        // 782
    const int WPN_GRID  = (NN * 32 + 255) / 256;     // 6250

    gemm_h2_kernel<true><<<GEMM_GRID, 256>>>(node_feat, wt + 0 * K2 * 128);
    agg_relu_kernel<<<WPN_GRID, 256>>>(W1, b1, hh1);
    gemm_h2_kernel<false><<<GEMM_GRID, 256>>>(hh1, wt + 1 * K2 * 128);
    agg_relu_kernel<<<WPN_GRID, 256>>>(Wmid + 0 * F * KDIM, bmid + 0 * F, hh0);
    gemm_h2_kernel<false><<<GEMM_GRID, 256>>>(hh0, wt + 2 * K2 * 128);
    agg_relu_kernel<<<WPN_GRID, 256>>>(Wmid + 1 * F * KDIM, bmid + 1 * F, hh1);
    gemm_h2_kernel<false><<<GEMM_GRID, 256>>>(hh1, wt + 3 * K2 * 128);
    agg_relu_kernel<<<WPN_GRID, 256>>>(Wmid + 2 * F * KDIM, bmid + 2 * F, hh0);
    gemm_h2_kernel<false><<<GEMM_GRID, 256>>>(hh0, wt + 4 * K2 * 128);
    agg_relu_kernel<<<WPN_GRID, 256>>>(Wmid + 3 * F * KDIM, bmid + 3 * F, hh1);
    gemm_h2_kernel<false><<<GEMM_GRID, 256>>>(hh1, wt + 5 * K2 * 128);
    agg_sigm_out_kernel<<<WPN_GRID, 256>>>(Wmid + 4 * F * KDIM, bmid + 4 * F, W2);

    out_agg_kernel<<<WPN_GRID, 256>>>(W2, b2, out);
}

// round 10
// speedup vs baseline: 3.1691x; 1.0914x over previous
#include <cuda_runtime.h>
#include <cuda_fp16.h>
#include <cstdint>
#include <math.h>

#define NN 50000
#define NE 800000
#define F 64
#define KDIM 129      // 2*F + 1
#define K2 32         // 64 k's as 32 half2 pairs

#define SCAN_CHUNK 256
#define SCAN_NBLK ((NN + SCAN_CHUNK - 1) / SCAN_CHUNK)   // 196

#define NBLK (148 * 3)   // persistent grid for fused layer kernels

// ---------------- scratch (static device globals — no allocation) ----------------
__device__ int    g_cnt[NN + 1];
__device__ int    g_rowptr[NN + 1];
__device__ int    g_rank[NE];
__device__ int    g_csr[NE];
__device__ int    g_bsum[SCAN_NBLK];
__device__ int    g_boff[SCAN_NBLK];
__device__ float  g_he[NN];
__device__ __align__(16) __half  g_p0[NN * F];
__device__ __align__(16) __half  g_q0[NN * F];
__device__ __align__(16) __half  g_p1[NN * F];
__device__ __align__(16) __half  g_q1[NN * F];
__device__ __align__(16) __half2 g_wt[6 * K2 * 128];   // [l][k2][n] half2 pairs
__device__ float4 g_pq2[NN];

// ---------------- prologue: CSR build ----------------
__global__ void hist_kernel(const float* __restrict__ ef, const int* __restrict__ dst) {
    int e = blockIdx.x * blockDim.x + threadIdx.x;
    if (e < NE) {
        int d = dst[e];
        g_rank[e] = atomicAdd(&g_cnt[d], 1);
        atomicAdd(&g_he[d], ef[e]);
    }
}

__device__ __forceinline__ int block_incl_scan(int v, int* smem) {
    const int t = threadIdx.x, lane = t & 31, w = t >> 5;
    int incl = v;
    #pragma unroll
    for (int off = 1; off < 32; off <<= 1) {
        int n = __shfl_up_sync(0xffffffffu, incl, off);
        if (lane >= off) incl += n;
    }
    if (lane == 31) smem[w] = incl;
    __syncthreads();
    if (w == 0) {
        int s = (lane < 8) ? smem[lane] : 0;
        #pragma unroll
        for (int off = 1; off < 8; off <<= 1) {
            int n = __shfl_up_sync(0xffffffffu, s, off);
            if (lane >= off) s += n;
        }
        if (lane < 8) smem[lane] = s;
    }
    __syncthreads();
    if (w > 0) incl += smem[w - 1];
    return incl;
}

__global__ void __launch_bounds__(256) scan1_kernel() {
    __shared__ int smem[8];
    int i = blockIdx.x * SCAN_CHUNK + threadIdx.x;
    int v = (i < NN) ? g_cnt[i] : 0;
    int incl = block_incl_scan(v, smem);
    if (threadIdx.x == 255) g_bsum[blockIdx.x] = incl;
}

__global__ void __launch_bounds__(256) scan2_kernel() {
    __shared__ int smem[8];
    int t = threadIdx.x;
    int v = (t < SCAN_NBLK) ? g_bsum[t] : 0;
    int incl = block_incl_scan(v, smem);
    if (t < SCAN_NBLK) g_boff[t] = incl - v;
    if (t == SCAN_NBLK - 1) g_rowptr[NN] = incl;
}

__global__ void __launch_bounds__(256) scan3_kernel() {
    __shared__ int smem[8];
    int i = blockIdx.x * SCAN_CHUNK + threadIdx.x;
    int v = (i < NN) ? g_cnt[i] : 0;
    int incl = block_incl_scan(v, smem);
    if (i < NN) g_rowptr[i] = g_boff[blockIdx.x] + incl - v;
}

__global__ void scatter_kernel(const int* __restrict__ src, const int* __restrict__ dst) {
    int e = blockIdx.x * blockDim.x + threadIdx.x;
    if (e < NE) {
        int d = dst[e];
        g_csr[g_rowptr[d] + g_rank[e]] = src[e];
    }
}

// ---------------- weight repack: g_wt[l][k2][n] = (Weff[n][2k2], Weff[n][2k2+1]) --
__global__ void convert_w_kernel(const float* __restrict__ W1, const float* __restrict__ Wmid) {
    int idx = blockIdx.x * blockDim.x + threadIdx.x;
    if (idx < 6 * K2 * 128) {
        int l = idx >> 12;
        int rem = idx & 4095;
        int k2 = rem >> 7;
        int n = rem & 127;
        const float* Wl = (l == 0) ? W1 : (Wmid + (l - 1) * F * KDIM);
        int k = 2 * k2;
        float v0, v1;
        if (n < F) { v0 = Wl[n * KDIM + k];            v1 = Wl[n * KDIM + k + 1]; }
        else       { v0 = Wl[(n - F) * KDIM + F + k];  v1 = Wl[(n - F) * KDIM + F + k + 1]; }
        g_wt[idx] = __floats2half2_rn(v0, v1);
    }
}

// ---------------- warp matvec: PQ[v] from h (half2 per lane, lane = k2) -------
// sW: uint4[K2][32]; lane computes outs 4*lane..4*lane+3.
// Writes fp16: outs<64 -> p_out, outs>=64 -> q_out.
__device__ __forceinline__ void warp_matvec2(
    const uint4* __restrict__ sW, unsigned h0u, unsigned h1u,
    int lane, int v0, int v1,
    __half* __restrict__ p_out, __half* __restrict__ q_out)
{
    float f0[4] = {0.f, 0.f, 0.f, 0.f};
    float f1[4] = {0.f, 0.f, 0.f, 0.f};

    #pragma unroll
    for (int chunk = 0; chunk < 2; chunk++) {
        __half2 a0[4], a1[4];
        #pragma unroll
        for (int j = 0; j < 4; j++) {
            a0[j] = __float2half2_rn(0.f);
            a1[j] = __float2half2_rn(0.f);
        }
        #pragma unroll
        for (int kk = 0; kk < 16; kk++) {
            const int k2 = chunk * 16 + kk;
            unsigned b0 = __shfl_sync(0xffffffffu, h0u, k2);
            unsigned b1 = __shfl_sync(0xffffffffu, h1u, k2);
            __half2 hb0 = *reinterpret_cast<__half2*>(&b0);
            __half2 hb1 = *reinterpret_cast<__half2*>(&b1);
            uint4 wv = sW[k2 * 32 + lane];
            __half2 w0 = *reinterpret_cast<__half2*>(&wv.x);
            __half2 w1 = *reinterpret_cast<__half2*>(&wv.y);
            __half2 w2 = *reinterpret_cast<__half2*>(&wv.z);
            __half2 w3 = *reinterpret_cast<__half2*>(&wv.w);
            a0[0] = __hfma2(hb0, w0, a0[0]);
            a0[1] = __hfma2(hb0, w1, a0[1]);
            a0[2] = __hfma2(hb0, w2, a0[2]);
            a0[3] = __hfma2(hb0, w3, a0[3]);
            a1[0] = __hfma2(hb1, w0, a1[0]);
            a1[1] = __hfma2(hb1, w1, a1[1]);
            a1[2] = __hfma2(hb1, w2, a1[2]);
            a1[3] = __hfma2(hb1, w3, a1[3]);
        }
        #pragma unroll
        for (int j = 0; j < 4; j++) {
            float2 t0 = __half22float2(a0[j]);
            float2 t1 = __half22float2(a1[j]);
            f0[j] += t0.x + t0.y;
            f1[j] += t1.x + t1.y;
        }
    }

    __half2 oA0 = __floats2half2_rn(f0[0], f0[1]);
    __half2 oB0 = __floats2half2_rn(f0[2], f0[3]);
    __half2 oA1 = __floats2half2_rn(f1[0], f1[1]);
    __half2 oB1 = __floats2half2_rn(f1[2], f1[3]);
    uint2 u0, u1;
    u0.x = *reinterpret_cast<unsigned*>(&oA0);
    u0.y = *reinterpret_cast<unsigned*>(&oB0);
    u1.x = *reinterpret_cast<unsigned*>(&oA1);
    u1.y = *reinterpret_cast<unsigned*>(&oB1);
    if (lane < 16) {
        *reinterpret_cast<uint2*>(p_out + v0 * F + 4 * lane) = u0;
        *reinterpret_cast<uint2*>(p_out + v1 * F + 4 * lane) = u1;
    } else {
        *reinterpret_cast<uint2*>(q_out + v0 * F + 4 * (lane - 16)) = u0;
        *reinterpret_cast<uint2*>(q_out + v1 * F + 4 * (lane - 16)) = u1;
    }
}

// ---------------- warp gather: acc = P[v] + sum Q[src] + whe*he + b -----------
__device__ __forceinline__ float2 warp_agg(
    const __half* __restrict__ p_in, const __half* __restrict__ q_in,
    int v, int c0, float whe0, float whe1, float b0, float b1)
{
    const float he = g_he[v];
    float2 p = __half22float2(*reinterpret_cast<const __half2*>(p_in + v * F + c0));
    float acc0 = p.x + b0 + whe0 * he;
    float acc1 = p.y + b1 + whe1 * he;

    const int js = g_rowptr[v];
    const int je = g_rowptr[v + 1];
    int j = js;
    for (; j + 8 <= je; j += 8) {
        int idx[8];
        #pragma unroll
        for (int u = 0; u < 8; u++) idx[u] = g_csr[j + u];
        float2 f[8];
        #pragma unroll
        for (int u = 0; u < 8; u++)
            f[u] = __half22float2(*reinterpret_cast<const __half2*>(q_in + idx[u] * F + c0));
        #pragma unroll
        for (int u = 0; u < 8; u++) { acc0 += f[u].x; acc1 += f[u].y; }
    }
    for (; j < je; j++) {
        float2 f = __half22float2(*reinterpret_cast<const __half2*>(q_in + g_csr[j] * F + c0));
        acc0 += f.x;
        acc1 += f.y;
    }
    return make_float2(acc0, acc1);
}

// ---------------- pre: PQ1[v] = W1eff . node_feat[v] (persistent) -------------
__global__ void __launch_bounds__(256) pre_kernel(
    const float* __restrict__ x,       // [NN, 64] fp32
    const __half2* __restrict__ wt,    // g_wt layer 0
    __half* __restrict__ p_out, __half* __restrict__ q_out)
{
    __shared__ uint4 sW[K2 * 32];
    const int tid = threadIdx.x;
    for (int i = tid; i < K2 * 32; i += 256)
        sW[i] = reinterpret_cast<const uint4*>(wt)[i];
    __syncthreads();

    const int lane = tid & 31;
    const int gwarp = (blockIdx.x * 256 + tid) >> 5;
    const int nwarps = (NBLK * 256) >> 5;

    for (int pp = gwarp; pp < NN / 2; pp += nwarps) {
        const int v0 = 2 * pp, v1 = v0 + 1;
        float2 x0 = *reinterpret_cast<const float2*>(x + v0 * F + 2 * lane);
        float2 x1 = *reinterpret_cast<const float2*>(x + v1 * F + 2 * lane);
        __half2 h0 = __floats2half2_rn(x0.x, x0.y);
        __half2 h1 = __floats2half2_rn(x1.x, x1.y);
        warp_matvec2(sW, *reinterpret_cast<unsigned*>(&h0),
                     *reinterpret_cast<unsigned*>(&h1), lane, v0, v1, p_out, q_out);
    }
}

// ---------------- fused layer: h = relu(agg(PQ_in)); PQ_out = Wt_next . h -----
__global__ void __launch_bounds__(256) fused_kernel(
    const __half* __restrict__ p_in, const __half* __restrict__ q_in,
    const float* __restrict__ Wcur,    // fp32 [64,129] for whe column
    const float* __restrict__ bias,
    const __half2* __restrict__ wt_next,
    __half* __restrict__ p_out, __half* __restrict__ q_out)
{
    __shared__ uint4 sW[K2 * 32];
    const int tid = threadIdx.x;
    for (int i = tid; i < K2 * 32; i += 256)
        sW[i] = reinterpret_cast<const uint4*>(wt_next)[i];
    __syncthreads();

    const int lane = tid & 31;
    const int c0 = 2 * lane;
    const float whe0 = Wcur[(c0 + 0) * KDIM + 128];
    const float whe1 = Wcur[(c0 + 1) * KDIM + 128];
    const float b0 = bias[c0 + 0];
    const float b1 = bias[c0 + 1];

    const int gwarp = (blockIdx.x * 256 + tid) >> 5;
    const int nwarps = (NBLK * 256) >> 5;

    for (int pp = gwarp; pp < NN / 2; pp += nwarps) {
        const int v0 = 2 * pp, v1 = v0 + 1;
        float2 a0 = warp_agg(p_in, q_in, v0, c0, whe0, whe1, b0, b1);
        float2 a1 = warp_agg(p_in, q_in, v1, c0, whe0, whe1, b0, b1);
        __half2 h0 = __floats2half2_rn(fmaxf(a0.x, 0.f), fmaxf(a0.y, 0.f));
        __half2 h1 = __floats2half2_rn(fmaxf(a1.x, 0.f), fmaxf(a1.y, 0.f));
        warp_matvec2(sW, *reinterpret_cast<unsigned*>(&h0),
                     *reinterpret_cast<unsigned*>(&h1), lane, v0, v1, p_out, q_out);
    }
}

// ---------------- last hidden (sigmoid) fused with out_pre --------------------
__global__ void __launch_bounds__(256) agg_sigm_out_kernel(
    const __half* __restrict__ p_in, const __half* __restrict__ q_in,
    const float* __restrict__ Wcur,
    const float* __restrict__ bias,
    const float* __restrict__ W2)
{
    const int v    = (blockIdx.x * blockDim.x + threadIdx.x) >> 5;
    const int lane = threadIdx.x & 31;
    if (v >= NN) return;

    const int c0 = 2 * lane;
    const float whe0 = Wcur[(c0 + 0) * KDIM + 128];
    const float whe1 = Wcur[(c0 + 1) * KDIM + 128];

    float2 a = warp_agg(p_in, q_in, v, c0, whe0, whe1, bias[c0], bias[c0 + 1]);
    const float h0 = 1.f / (1.f + __expf(-a.x));
    const float h1 = 1.f / (1.f + __expf(-a.y));

    float p0 = W2[c0] * h0 + W2[c0 + 1] * h1;
    float p1 = W2[KDIM + c0] * h0 + W2[KDIM + c0 + 1] * h1;
    float q0 = W2[64 + c0] * h0 + W2[64 + c0 + 1] * h1;
    float q1 = W2[KDIM + 64 + c0] * h0 + W2[KDIM + 64 + c0 + 1] * h1;

    #pragma unroll
    for (int off = 16; off > 0; off >>= 1) {
        p0 += __shfl_xor_sync(0xffffffffu, p0, off);
        p1 += __shfl_xor_sync(0xffffffffu, p1, off);
        q0 += __shfl_xor_sync(0xffffffffu, q0, off);
        q1 += __shfl_xor_sync(0xffffffffu, q1, off);
    }
    if (lane == 0) g_pq2[v] = make_float4(p0, p1, q0, q1);
}

// ---------------- final layer: edge-parallel q2 sum --------------------------
__global__ void __launch_bounds__(256) out_agg_kernel(
    const float* __restrict__ W2,
    const float* __restrict__ b2,
    float* __restrict__ out)
{
    const int v    = (blockIdx.x * blockDim.x + threadIdx.x) >> 5;
    const int lane = threadIdx.x & 31;
    if (v >= NN) return;

    const int js = g_rowptr[v];
    const int je = g_rowptr[v + 1];
    float acc0 = 0.f, acc1 = 0.f;
    for (int j = js + lane; j < je; j += 32) {
        float4 pq = g_pq2[g_csr[j]];
        acc0 += pq.z;
        acc1 += pq.w;
    }
    #pragma unroll
    for (int off = 16; off > 0; off >>= 1) {
        acc0 += __shfl_xor_sync(0xffffffffu, acc0, off);
        acc1 += __shfl_xor_sync(0xffffffffu, acc1, off);
    }
    if (lane == 0) {
        float4 mine = g_pq2[v];
        float he = g_he[v];
        out[v * 2 + 0] = mine.x + acc0 + W2[128]        * he + b2[0];
        out[v * 2 + 1] = mine.y + acc1 + W2[KDIM + 128] * he + b2[1];
    }
}

// ---------------- launch ----------------
extern "C" void kernel_launch(void* const* d_in, const int* in_sizes, int n_in,
                              void* d_out, int out_size)
{
    const float* node_feat = (const float*)d_in[0];
    const float* edge_feat = (const float*)d_in[1];
    const int*   src       = (const int*)  d_in[2];
    const int*   dst       = (const int*)  d_in[3];
    const float* W1        = (const float*)d_in[4];
    const float* b1        = (const float*)d_in[5];
    const float* Wmid      = (const float*)d_in[6];
    const float* bmid      = (const float*)d_in[7];
    const float* W2        = (const float*)d_in[8];
    const float* b2        = (const float*)d_in[9];
    float*       out       = (float*)d_out;

    __half *p0, *q0, *p1, *q1;
    __half2* wt;
    void *cnt_ptr, *he_ptr;
    cudaGetSymbolAddress((void**)&p0, g_p0);
    cudaGetSymbolAddress((void**)&q0, g_q0);
    cudaGetSymbolAddress((void**)&p1, g_p1);
    cudaGetSymbolAddress((void**)&q1, g_q1);
    cudaGetSymbolAddress((void**)&wt, g_wt);
    cudaGetSymbolAddress(&cnt_ptr, g_cnt);
    cudaGetSymbolAddress(&he_ptr,  g_he);

    cudaMemsetAsync(cnt_ptr, 0, (NN + 1) * sizeof(int));
    cudaMemsetAsync(he_ptr,  0, NN * sizeof(float));
    hist_kernel<<<(NE + 255) / 256, 256>>>(edge_feat, dst);
    convert_w_kernel<<<(6 * K2 * 128 + 255) / 256, 256>>>(W1, Wmid);
    scan1_kernel<<<SCAN_NBLK, 256>>>();
    scan2_kernel<<<1, 256>>>();
    scan3_kernel<<<SCAN_NBLK, 256>>>();
    scatter_kernel<<<(NE + 255) / 256, 256>>>(src, dst);

    const int WPN_GRID = (NN * 32 + 255) / 256;   // 6250

    // PQ1 = W1eff . x
    pre_kernel<<<NBLK, 256>>>(node_feat, wt + 0 * K2 * 128, p0, q0);
    // h1..h5 (relu) fused with next-layer matvec; ping-pong buffers
    fused_kernel<<<NBLK, 256>>>(p0, q0, W1, b1, wt + 1 * K2 * 128, p1, q1);
    fused_kernel<<<NBLK, 256>>>(p1, q1, Wmid + 0 * F * KDIM, bmid + 0 * F, wt + 2 * K2 * 128, p0, q0);
    fused_kernel<<<NBLK, 256>>>(p0, q0, Wmid + 1 * F * KDIM, bmid + 1 * F, wt + 3 * K2 * 128, p1, q1);
    fused_kernel<<<NBLK, 256>>>(p1, q1, Wmid + 2 * F * KDIM, bmid + 2 * F, wt + 4 * K2 * 128, p0, q0);
    fused_kernel<<<NBLK, 256>>>(p0, q0, Wmid + 3 * F * KDIM, bmid + 3 * F, wt + 5 * K2 * 128, p1, q1);
    // h6 (sigmoid) + out_pre
    agg_sigm_out_kernel<<<WPN_GRID, 256>>>(p1, q1, Wmid + 4 * F * KDIM, bmid + 4 * F, W2);
    out_agg_kernel<<<WPN_GRID, 256>>>(W2, b2, out);
}

// round 11
// speedup vs baseline: 3.3131x; 1.0454x over previous
#include <cuda_runtime.h>
#include <cuda_fp16.h>
#include <cstdint>
#include <math.h>

#define NN 50000
#define NE 800000
#define F 64
#define KDIM 129      // 2*F + 1
#define K2 32         // 64 k's as 32 half2 pairs

#define SCAN_CHUNK 256
#define SCAN_NBLK ((NN + SCAN_CHUNK - 1) / SCAN_CHUNK)   // 196

#define NBLK (148 * 3)   // persistent grid for fused layer kernels

// ---------------- scratch (static device globals — no allocation) ----------------
__device__ int    g_cnt[NN + 1];
__device__ int    g_rowptr[NN + 1];
__device__ int    g_rank[NE];
__device__ int    g_csr[NE];
__device__ int    g_bsum[SCAN_NBLK];
__device__ int    g_boff[SCAN_NBLK];
__device__ float  g_he[NN];
__device__ __align__(16) __half  g_p0[NN * F];
__device__ __align__(16) __half  g_q0[NN * F];
__device__ __align__(16) __half  g_p1[NN * F];
__device__ __align__(16) __half  g_q1[NN * F];
__device__ __align__(16) __half2 g_wt[6 * K2 * 128];   // [l][k2][n] half2 pairs
__device__ float2 g_p2[NN];      // final layer self part (p2_0, p2_1)
__device__ float2 g_q2[NN];      // final layer aggr part (q2_0, q2_1) — gathered

// ---------------- prologue: CSR build ----------------
__global__ void hist_kernel(const float* __restrict__ ef, const int* __restrict__ dst) {
    int e = blockIdx.x * blockDim.x + threadIdx.x;
    if (e < NE) {
        int d = dst[e];
        g_rank[e] = atomicAdd(&g_cnt[d], 1);
        atomicAdd(&g_he[d], ef[e]);
    }
}

__device__ __forceinline__ int block_incl_scan(int v, int* smem) {
    const int t = threadIdx.x, lane = t & 31, w = t >> 5;
    int incl = v;
    #pragma unroll
    for (int off = 1; off < 32; off <<= 1) {
        int n = __shfl_up_sync(0xffffffffu, incl, off);
        if (lane >= off) incl += n;
    }
    if (lane == 31) smem[w] = incl;
    __syncthreads();
    if (w == 0) {
        int s = (lane < 8) ? smem[lane] : 0;
        #pragma unroll
        for (int off = 1; off < 8; off <<= 1) {
            int n = __shfl_up_sync(0xffffffffu, s, off);
            if (lane >= off) s += n;
        }
        if (lane < 8) smem[lane] = s;
    }
    __syncthreads();
    if (w > 0) incl += smem[w - 1];
    return incl;
}

__global__ void __launch_bounds__(256) scan1_kernel() {
    __shared__ int smem[8];
    int i = blockIdx.x * SCAN_CHUNK + threadIdx.x;
    int v = (i < NN) ? g_cnt[i] : 0;
    int incl = block_incl_scan(v, smem);
    if (threadIdx.x == 255) g_bsum[blockIdx.x] = incl;
}

__global__ void __launch_bounds__(256) scan2_kernel() {
    __shared__ int smem[8];
    int t = threadIdx.x;
    int v = (t < SCAN_NBLK) ? g_bsum[t] : 0;
    int incl = block_incl_scan(v, smem);
    if (t < SCAN_NBLK) g_boff[t] = incl - v;
    if (t == SCAN_NBLK - 1) g_rowptr[NN] = incl;
}

__global__ void __launch_bounds__(256) scan3_kernel() {
    __shared__ int smem[8];
    int i = blockIdx.x * SCAN_CHUNK + threadIdx.x;
    int v = (i < NN) ? g_cnt[i] : 0;
    int incl = block_incl_scan(v, smem);
    if (i < NN) g_rowptr[i] = g_boff[blockIdx.x] + incl - v;
}

__global__ void scatter_kernel(const int* __restrict__ src, const int* __restrict__ dst) {
    int e = blockIdx.x * blockDim.x + threadIdx.x;
    if (e < NE) {
        int d = dst[e];
        g_csr[g_rowptr[d] + g_rank[e]] = src[e];
    }
}

// ---------------- weight repack ----------------
__global__ void convert_w_kernel(const float* __restrict__ W1, const float* __restrict__ Wmid) {
    int idx = blockIdx.x * blockDim.x + threadIdx.x;
    if (idx < 6 * K2 * 128) {
        int l = idx >> 12;
        int rem = idx & 4095;
        int k2 = rem >> 7;
        int n = rem & 127;
        const float* Wl = (l == 0) ? W1 : (Wmid + (l - 1) * F * KDIM);
        int k = 2 * k2;
        float v0, v1;
        if (n < F) { v0 = Wl[n * KDIM + k];            v1 = Wl[n * KDIM + k + 1]; }
        else       { v0 = Wl[(n - F) * KDIM + F + k];  v1 = Wl[(n - F) * KDIM + F + k + 1]; }
        g_wt[idx] = __floats2half2_rn(v0, v1);
    }
}

// ---------------- warp matvec: PQ for node pair ------------------------------
__device__ __forceinline__ void warp_matvec2(
    const uint4* __restrict__ sW, unsigned h0u, unsigned h1u,
    int lane, int v0, int v1,
    __half* __restrict__ p_out, __half* __restrict__ q_out)
{
    float f0[4] = {0.f, 0.f, 0.f, 0.f};
    float f1[4] = {0.f, 0.f, 0.f, 0.f};

    #pragma unroll
    for (int chunk = 0; chunk < 2; chunk++) {
        __half2 a0[4], a1[4];
        #pragma unroll
        for (int j = 0; j < 4; j++) {
            a0[j] = __float2half2_rn(0.f);
            a1[j] = __float2half2_rn(0.f);
        }
        #pragma unroll
        for (int kk = 0; kk < 16; kk++) {
            const int k2 = chunk * 16 + kk;
            unsigned b0 = __shfl_sync(0xffffffffu, h0u, k2);
            unsigned b1 = __shfl_sync(0xffffffffu, h1u, k2);
            __half2 hb0 = *reinterpret_cast<__half2*>(&b0);
            __half2 hb1 = *reinterpret_cast<__half2*>(&b1);
            uint4 wv = sW[k2 * 32 + lane];
            __half2 w0 = *reinterpret_cast<__half2*>(&wv.x);
            __half2 w1 = *reinterpret_cast<__half2*>(&wv.y);
            __half2 w2 = *reinterpret_cast<__half2*>(&wv.z);
            __half2 w3 = *reinterpret_cast<__half2*>(&wv.w);
            a0[0] = __hfma2(hb0, w0, a0[0]);
            a0[1] = __hfma2(hb0, w1, a0[1]);
            a0[2] = __hfma2(hb0, w2, a0[2]);
            a0[3] = __hfma2(hb0, w3, a0[3]);
            a1[0] = __hfma2(hb1, w0, a1[0]);
            a1[1] = __hfma2(hb1, w1, a1[1]);
            a1[2] = __hfma2(hb1, w2, a1[2]);
            a1[3] = __hfma2(hb1, w3, a1[3]);
        }
        #pragma unroll
        for (int j = 0; j < 4; j++) {
            float2 t0 = __half22float2(a0[j]);
            float2 t1 = __half22float2(a1[j]);
            f0[j] += t0.x + t0.y;
            f1[j] += t1.x + t1.y;
        }
    }

    __half2 oA0 = __floats2half2_rn(f0[0], f0[1]);
    __half2 oB0 = __floats2half2_rn(f0[2], f0[3]);
    __half2 oA1 = __floats2half2_rn(f1[0], f1[1]);
    __half2 oB1 = __floats2half2_rn(f1[2], f1[3]);
    uint2 u0, u1;
    u0.x = *reinterpret_cast<unsigned*>(&oA0);
    u0.y = *reinterpret_cast<unsigned*>(&oB0);
    u1.x = *reinterpret_cast<unsigned*>(&oA1);
    u1.y = *reinterpret_cast<unsigned*>(&oB1);
    if (lane < 16) {
        *reinterpret_cast<uint2*>(p_out + v0 * F + 4 * lane) = u0;
        *reinterpret_cast<uint2*>(p_out + v1 * F + 4 * lane) = u1;
    } else {
        *reinterpret_cast<uint2*>(q_out + v0 * F + 4 * (lane - 16)) = u0;
        *reinterpret_cast<uint2*>(q_out + v1 * F + 4 * (lane - 16)) = u1;
    }
}

// ---------------- interleaved dual-node gather (MLP 16) -----------------------
// returns (acc for v0).xy, (acc for v1).zw
__device__ __forceinline__ float4 warp_agg2(
    const __half* __restrict__ p_in, const __half* __restrict__ q_in,
    int v0, int v1, int c0, float whe0, float whe1, float b0, float b1)
{
    const float heA = g_he[v0];
    const float heB = g_he[v1];
    float2 pA = __half22float2(*reinterpret_cast<const __half2*>(p_in + v0 * F + c0));
    float2 pB = __half22float2(*reinterpret_cast<const __half2*>(p_in + v1 * F + c0));
    float a0 = pA.x + b0 + whe0 * heA;
    float a1 = pA.y + b1 + whe1 * heA;
    float a2 = pB.x + b0 + whe0 * heB;
    float a3 = pB.y + b1 + whe1 * heB;

    int j0 = g_rowptr[v0];
    const int e0 = g_rowptr[v0 + 1];
    int j1 = g_rowptr[v1];
    const int e1 = g_rowptr[v1 + 1];

    // main interleaved loop: both nodes, 8 loads each in flight (16 total)
    while (j0 + 8 <= e0 && j1 + 8 <= e1) {
        int i0[8], i1[8];
        #pragma unroll
        for (int u = 0; u < 8; u++) i0[u] = g_csr[j0 + u];
        #pragma unroll
        for (int u = 0; u < 8; u++) i1[u] = g_csr[j1 + u];
        float2 f0[8], f1[8];
        #pragma unroll
        for (int u = 0; u < 8; u++)
            f0[u] = __half22float2(*reinterpret_cast<const __half2*>(q_in + i0[u] * F + c0));
        #pragma unroll
        for (int u = 0; u < 8; u++)
            f1[u] = __half22float2(*reinterpret_cast<const __half2*>(q_in + i1[u] * F + c0));
        #pragma unroll
        for (int u = 0; u < 8; u++) { a0 += f0[u].x; a1 += f0[u].y; }
        #pragma unroll
        for (int u = 0; u < 8; u++) { a2 += f1[u].x; a3 += f1[u].y; }
        j0 += 8;
        j1 += 8;
    }
    // tails (8-unrolled then scalar) for each node
    for (; j0 + 8 <= e0; j0 += 8) {
        int i0[8];
        #pragma unroll
        for (int u = 0; u < 8; u++) i0[u] = g_csr[j0 + u];
        float2 f0[8];
        #pragma unroll
        for (int u = 0; u < 8; u++)
            f0[u] = __half22float2(*reinterpret_cast<const __half2*>(q_in + i0[u] * F + c0));
        #pragma unroll
        for (int u = 0; u < 8; u++) { a0 += f0[u].x; a1 += f0[u].y; }
    }
    for (; j0 < e0; j0++) {
        float2 f = __half22float2(*reinterpret_cast<const __half2*>(q_in + g_csr[j0] * F + c0));
        a0 += f.x;
        a1 += f.y;
    }
    for (; j1 + 8 <= e1; j1 += 8) {
        int i1[8];
        #pragma unroll
        for (int u = 0; u < 8; u++) i1[u] = g_csr[j1 + u];
        float2 f1[8];
        #pragma unroll
        for (int u = 0; u < 8; u++)
            f1[u] = __half22float2(*reinterpret_cast<const __half2*>(q_in + i1[u] * F + c0));
        #pragma unroll
        for (int u = 0; u < 8; u++) { a2 += f1[u].x; a3 += f1[u].y; }
    }
    for (; j1 < e1; j1++) {
        float2 f = __half22float2(*reinterpret_cast<const __half2*>(q_in + g_csr[j1] * F + c0));
        a2 += f.x;
        a3 += f.y;
    }
    return make_float4(a0, a1, a2, a3);
}

// single-node gather (for the sigmoid/out kernel)
__device__ __forceinline__ float2 warp_agg(
    const __half* __restrict__ p_in, const __half* __restrict__ q_in,
    int v, int c0, float whe0, float whe1, float b0, float b1)
{
    const float he = g_he[v];
    float2 p = __half22float2(*reinterpret_cast<const __half2*>(p_in + v * F + c0));
    float acc0 = p.x + b0 + whe0 * he;
    float acc1 = p.y + b1 + whe1 * he;

    int j = g_rowptr[v];
    const int je = g_rowptr[v + 1];
    for (; j + 8 <= je; j += 8) {
        int idx[8];
        #pragma unroll
        for (int u = 0; u < 8; u++) idx[u] = g_csr[j + u];
        float2 f[8];
        #pragma unroll
        for (int u = 0; u < 8; u++)
            f[u] = __half22float2(*reinterpret_cast<const __half2*>(q_in + idx[u] * F + c0));
        #pragma unroll
        for (int u = 0; u < 8; u++) { acc0 += f[u].x; acc1 += f[u].y; }
    }
    for (; j < je; j++) {
        float2 f = __half22float2(*reinterpret_cast<const __half2*>(q_in + g_csr[j] * F + c0));
        acc0 += f.x;
        acc1 += f.y;
    }
    return make_float2(acc0, acc1);
}

// ---------------- pre: PQ1[v] = W1eff . node_feat[v] (persistent) -------------
__global__ void __launch_bounds__(256) pre_kernel(
    const float* __restrict__ x,
    const __half2* __restrict__ wt,
    __half* __restrict__ p_out, __half* __restrict__ q_out)
{
    __shared__ uint4 sW[K2 * 32];
    const int tid = threadIdx.x;
    for (int i = tid; i < K2 * 32; i += 256)
        sW[i] = reinterpret_cast<const uint4*>(wt)[i];
    __syncthreads();

    const int lane = tid & 31;
    const int gwarp = (blockIdx.x * 256 + tid) >> 5;
    const int nwarps = (NBLK * 256) >> 5;

    for (int pp = gwarp; pp < NN / 2; pp += nwarps) {
        const int v0 = 2 * pp, v1 = v0 + 1;
        float2 x0 = *reinterpret_cast<const float2*>(x + v0 * F + 2 * lane);
        float2 x1 = *reinterpret_cast<const float2*>(x + v1 * F + 2 * lane);
        __half2 h0 = __floats2half2_rn(x0.x, x0.y);
        __half2 h1 = __floats2half2_rn(x1.x, x1.y);
        warp_matvec2(sW, *reinterpret_cast<unsigned*>(&h0),
                     *reinterpret_cast<unsigned*>(&h1), lane, v0, v1, p_out, q_out);
    }
}

// ---------------- fused layer: h = relu(agg(PQ_in)); PQ_out = Wt_next . h -----
__global__ void __launch_bounds__(256) fused_kernel(
    const __half* __restrict__ p_in, const __half* __restrict__ q_in,
    const float* __restrict__ Wcur,
    const float* __restrict__ bias,
    const __half2* __restrict__ wt_next,
    __half* __restrict__ p_out, __half* __restrict__ q_out)
{
    __shared__ uint4 sW[K2 * 32];
    const int tid = threadIdx.x;
    for (int i = tid; i < K2 * 32; i += 256)
        sW[i] = reinterpret_cast<const uint4*>(wt_next)[i];
    __syncthreads();

    const int lane = tid & 31;
    const int c0 = 2 * lane;
    const float whe0 = Wcur[(c0 + 0) * KDIM + 128];
    const float whe1 = Wcur[(c0 + 1) * KDIM + 128];
    const float b0 = bias[c0 + 0];
    const float b1 = bias[c0 + 1];

    const int gwarp = (blockIdx.x * 256 + tid) >> 5;
    const int nwarps = (NBLK * 256) >> 5;

    for (int pp = gwarp; pp < NN / 2; pp += nwarps) {
        const int v0 = 2 * pp, v1 = v0 + 1;
        float4 a = warp_agg2(p_in, q_in, v0, v1, c0, whe0, whe1, b0, b1);
        __half2 h0 = __floats2half2_rn(fmaxf(a.x, 0.f), fmaxf(a.y, 0.f));
        __half2 h1 = __floats2half2_rn(fmaxf(a.z, 0.f), fmaxf(a.w, 0.f));
        warp_matvec2(sW, *reinterpret_cast<unsigned*>(&h0),
                     *reinterpret_cast<unsigned*>(&h1), lane, v0, v1, p_out, q_out);
    }
}

// ---------------- last hidden (sigmoid) fused with out_pre --------------------
__global__ void __launch_bounds__(256) agg_sigm_out_kernel(
    const __half* __restrict__ p_in, const __half* __restrict__ q_in,
    const float* __restrict__ Wcur,
    const float* __restrict__ bias,
    const float* __restrict__ W2)
{
    const int v    = (blockIdx.x * blockDim.x + threadIdx.x) >> 5;
    const int lane = threadIdx.x & 31;
    if (v >= NN) return;

    const int c0 = 2 * lane;
    const float whe0 = Wcur[(c0 + 0) * KDIM + 128];
    const float whe1 = Wcur[(c0 + 1) * KDIM + 128];

    float2 a = warp_agg(p_in, q_in, v, c0, whe0, whe1, bias[c0], bias[c0 + 1]);
    const float h0 = 1.f / (1.f + __expf(-a.x));
    const float h1 = 1.f / (1.f + __expf(-a.y));

    float p0 = W2[c0] * h0 + W2[c0 + 1] * h1;
    float p1 = W2[KDIM + c0] * h0 + W2[KDIM + c0 + 1] * h1;
    float q0 = W2[64 + c0] * h0 + W2[64 + c0 + 1] * h1;
    float q1 = W2[KDIM + 64 + c0] * h0 + W2[KDIM + 64 + c0 + 1] * h1;

    #pragma unroll
    for (int off = 16; off > 0; off >>= 1) {
        p0 += __shfl_xor_sync(0xffffffffu, p0, off);
        p1 += __shfl_xor_sync(0xffffffffu, p1, off);
        q0 += __shfl_xor_sync(0xffffffffu, q0, off);
        q1 += __shfl_xor_sync(0xffffffffu, q1, off);
    }
    if (lane == 0) {
        g_p2[v] = make_float2(p0, p1);
        g_q2[v] = make_float2(q0, q1);
    }
}

// ---------------- final layer: edge-parallel q2 sum (8 B/edge) ----------------
__global__ void __launch_bounds__(256) out_agg_kernel(
    const float* __restrict__ W2,
    const float* __restrict__ b2,
    float* __restrict__ out)
{
    const int v    = (blockIdx.x * blockDim.x + threadIdx.x) >> 5;
    const int lane = threadIdx.x & 31;
    if (v >= NN) return;

    const int js = g_rowptr[v];
    const int je = g_rowptr[v + 1];
    float acc0 = 0.f, acc1 = 0.f;
    for (int j = js + lane; j < je; j += 32) {
        float2 q = g_q2[g_csr[j]];
        acc0 += q.x;
        acc1 += q.y;
    }
    #pragma unroll
    for (int off = 16; off > 0; off >>= 1) {
        acc0 += __shfl_xor_sync(0xffffffffu, acc0, off);
        acc1 += __shfl_xor_sync(0xffffffffu, acc1, off);
    }
    if (lane == 0) {
        float2 mine = g_p2[v];
        float he = g_he[v];
        out[v * 2 + 0] = mine.x + acc0 + W2[128]        * he + b2[0];
        out[v * 2 + 1] = mine.y + acc1 + W2[KDIM + 128] * he + b2[1];
    }
}

// ---------------- launch ----------------
extern "C" void kernel_launch(void* const* d_in, const int* in_sizes, int n_in,
                              void* d_out, int out_size)
{
    const float* node_feat = (const float*)d_in[0];
    const float* edge_feat = (const float*)d_in[1];
    const int*   src       = (const int*)  d_in[2];
    const int*   dst       = (const int*)  d_in[3];
    const float* W1        = (const float*)d_in[4];
    const float* b1        = (const float*)d_in[5];
    const float* Wmid      = (const float*)d_in[6];
    const float* bmid      = (const float*)d_in[7];
    const float* W2        = (const float*)d_in[8];
    const float* b2        = (const float*)d_in[9];
    float*       out       = (float*)d_out;

    __half *p0, *q0, *p1, *q1;
    __half2* wt;
    void *cnt_ptr, *he_ptr;
    cudaGetSymbolAddress((void**)&p0, g_p0);
    cudaGetSymbolAddress((void**)&q0, g_q0);
    cudaGetSymbolAddress((void**)&p1, g_p1);
    cudaGetSymbolAddress((void**)&q1, g_q1);
    cudaGetSymbolAddress((void**)&wt, g_wt);
    cudaGetSymbolAddress(&cnt_ptr, g_cnt);
    cudaGetSymbolAddress(&he_ptr,  g_he);

    cudaMemsetAsync(cnt_ptr, 0, (NN + 1) * sizeof(int));
    cudaMemsetAsync(he_ptr,  0, NN * sizeof(float));
    hist_kernel<<<(NE + 255) / 256, 256>>>(edge_feat, dst);
    convert_w_kernel<<<(6 * K2 * 128 + 255) / 256, 256>>>(W1, Wmid);
    scan1_kernel<<<SCAN_NBLK, 256>>>();
    scan2_kernel<<<1, 256>>>();
    scan3_kernel<<<SCAN_NBLK, 256>>>();
    scatter_kernel<<<(NE + 255) / 256, 256>>>(src, dst);

    const int WPN_GRID = (NN * 32 + 255) / 256;   // 6250

    pre_kernel<<<NBLK, 256>>>(node_feat, wt + 0 * K2 * 128, p0, q0);
    fused_kernel<<<NBLK, 256>>>(p0, q0, W1, b1, wt + 1 * K2 * 128, p1, q1);
    fused_kernel<<<NBLK, 256>>>(p1, q1, Wmid + 0 * F * KDIM, bmid + 0 * F, wt + 2 * K2 * 128, p0, q0);
    fused_kernel<<<NBLK, 256>>>(p0, q0, Wmid + 1 * F * KDIM, bmid + 1 * F, wt + 3 * K2 * 128, p1, q1);
    fused_kernel<<<NBLK, 256>>>(p1, q1, Wmid + 2 * F * KDIM, bmid + 2 * F, wt + 4 * K2 * 128, p0, q0);
    fused_kernel<<<NBLK, 256>>>(p0, q0, Wmid + 3 * F * KDIM, bmid + 3 * F, wt + 5 * K2 * 128, p1, q1);
    agg_sigm_out_kernel<<<WPN_GRID, 256>>>(p1, q1, Wmid + 4 * F * KDIM, bmid + 4 * F, W2);
    out_agg_kernel<<<WPN_GRID, 256>>>(W2, b2, out);
}